// round 1
// baseline (speedup 1.0000x reference)
#include <cuda_runtime.h>
#include <cstdio>

#define B_ 2
#define T_ 2048
#define C_ 2048
#define H_ 16
#define D_ 128

// ---------------- scratch (device globals: no runtime allocation) ----------------
__device__ float g_qkv[(size_t)B_ * T_ * 3 * C_];     // 100.7 MB
__device__ float g_Q[(size_t)B_ * H_ * T_ * D_];      // 33.5 MB
__device__ float g_K[(size_t)B_ * H_ * T_ * D_];
__device__ float g_V[(size_t)B_ * H_ * T_ * D_];
__device__ float g_attn[(size_t)B_ * T_ * C_];        // 33.5 MB

// ---------------- SGEMM: C[M,N] = A[M,K] @ B[K,N], all row-major, fp32 ----------
#define BM 128
#define BN 128
#define BK 8
#define TM 8
#define TN 8

__global__ __launch_bounds__(256) void sgemm_kernel(
    const float* __restrict__ A, const float* __restrict__ Bm, float* __restrict__ Cm,
    int M, int N, int K)
{
    __shared__ float As[BK][BM];
    __shared__ float Bs[BK][BN];

    const int tid = threadIdx.x;
    const int m0 = blockIdx.y * BM;
    const int n0 = blockIdx.x * BN;

    const int ty = tid / 16;          // 0..15
    const int tx = tid % 16;          // 0..15

    const int aRow = tid >> 1;        // 0..127
    const int aCol = (tid & 1) * 4;   // 0 or 4
    const int bRow = tid >> 5;        // 0..7
    const int bCol = (tid & 31) * 4;  // 0..124

    float acc[TM][TN];
#pragma unroll
    for (int i = 0; i < TM; i++)
#pragma unroll
        for (int j = 0; j < TN; j++) acc[i][j] = 0.0f;

    const float* Ap = A + (size_t)(m0 + aRow) * K + aCol;
    const float* Bp = Bm + (size_t)bRow * N + n0 + bCol;

    for (int k0 = 0; k0 < K; k0 += BK) {
        float4 a4 = *(const float4*)(Ap + k0);
        As[aCol + 0][aRow] = a4.x;
        As[aCol + 1][aRow] = a4.y;
        As[aCol + 2][aRow] = a4.z;
        As[aCol + 3][aRow] = a4.w;
        float4 b4 = *(const float4*)(Bp + (size_t)k0 * N);
        *(float4*)&Bs[bRow][bCol] = b4;
        __syncthreads();

#pragma unroll
        for (int k = 0; k < BK; k++) {
            float regM[TM], regN[TN];
#pragma unroll
            for (int i = 0; i < TM; i++) regM[i] = As[k][ty * TM + i];
#pragma unroll
            for (int j = 0; j < TN; j++) regN[j] = Bs[k][tx * TN + j];
#pragma unroll
            for (int i = 0; i < TM; i++)
#pragma unroll
                for (int j = 0; j < TN; j++)
                    acc[i][j] += regM[i] * regN[j];
        }
        __syncthreads();
    }

#pragma unroll
    for (int i = 0; i < TM; i++) {
        float* cp = Cm + (size_t)(m0 + ty * TM + i) * N + n0 + tx * TN;
        *(float4*)cp       = make_float4(acc[i][0], acc[i][1], acc[i][2], acc[i][3]);
        *(float4*)(cp + 4) = make_float4(acc[i][4], acc[i][5], acc[i][6], acc[i][7]);
    }
}

// ---------------- RoPE + split/transpose: qkv [B,T,3C] -> Q/K/V [B,H,T,D] -------
__global__ __launch_bounds__(128) void rope_split_kernel(
    const float* __restrict__ qkv, const float* __restrict__ cosg,
    const float* __restrict__ sing,
    float* __restrict__ Q, float* __restrict__ K, float* __restrict__ V)
{
    const int h = blockIdx.x;
    const int t = blockIdx.y;
    const int b = blockIdx.z;
    const int d = threadIdx.x;  // 0..127

    const float* base = qkv + ((size_t)(b * T_ + t)) * (3 * C_) + h * D_;
    const size_t outBase = ((size_t)((b * H_ + h) * T_ + t)) * D_;

    // V: plain copy/transpose
    V[outBase + d] = base[2 * C_ + d];

    if (d < D_ / 2) {
        const float c = cosg[t * (D_ / 2) + d];
        const float s = sing[t * (D_ / 2) + d];
        // Q
        float q1 = base[d];
        float q2 = base[d + D_ / 2];
        Q[outBase + d]          = q1 * c - q2 * s;
        Q[outBase + d + D_ / 2] = q1 * s + q2 * c;
        // K
        float k1 = base[C_ + d];
        float k2 = base[C_ + d + D_ / 2];
        K[outBase + d]          = k1 * c - k2 * s;
        K[outBase + d + D_ / 2] = k1 * s + k2 * c;
    }
}

// ---------------- causal flash attention, fp32 ---------------------------------
// grid: (T/BQ, B*H), 128 threads. BQ=64 queries, BKV=32 keys per tile.
// thread (rg = tid/8 in [0,16), cg = tid%8): scores 4 rows x 4 cols,
// output 4 rows x 16 cols (cols = cg*4 + 32*cc + w).
#define BQ 64
#define BKV 32
#define QS_STR 132
#define KS_STR 132
#define PS_STR 33
// dynamic smem floats: Qs 64*132, Ks 32*132, Vs 32*132, Ps 64*33
#define ATTN_SMEM_FLOATS (64 * QS_STR + 32 * KS_STR + 32 * KS_STR + 64 * PS_STR)

__global__ __launch_bounds__(128) void attn_kernel(
    const float* __restrict__ Q, const float* __restrict__ K,
    const float* __restrict__ V, float* __restrict__ Out)
{
    extern __shared__ float smem[];
    float* Qs = smem;
    float* Ks = Qs + 64 * QS_STR;
    float* Vs = Ks + 32 * KS_STR;
    float* Ps = Vs + 32 * KS_STR;

    const int qb = blockIdx.x;
    const int bh = blockIdx.y;
    const int b = bh / H_;
    const int h = bh % H_;
    const int tid = threadIdx.x;
    const int rg = tid >> 3;
    const int cg = tid & 7;
    const int q0 = qb * BQ;

    const float* Qg = Q + ((size_t)bh * T_ + q0) * D_;
    const float* Kg = K + (size_t)bh * T_ * D_;
    const float* Vg = V + (size_t)bh * T_ * D_;

    // load Q tile: 64x128 floats = 2048 float4s, 16 per thread
#pragma unroll
    for (int i = 0; i < 16; i++) {
        int idx = tid + i * 128;
        int r = idx >> 5, c4 = (idx & 31) * 4;
        *(float4*)&Qs[r * QS_STR + c4] = *(const float4*)(Qg + (size_t)r * D_ + c4);
    }

    float m[4], l[4], acc[4][16];
#pragma unroll
    for (int i = 0; i < 4; i++) {
        m[i] = -1e30f;
        l[i] = 0.0f;
#pragma unroll
        for (int c = 0; c < 16; c++) acc[i][c] = 0.0f;
    }

    const float scale = 0.08838834764831845f;  // 1/sqrt(128)
    const int nkv = (q0 + BQ) / BKV;

    for (int kt = 0; kt < nkv; kt++) {
        __syncthreads();
        // load K,V tiles: 32x128 = 1024 float4s each, 8 per thread
#pragma unroll
        for (int i = 0; i < 8; i++) {
            int idx = tid + i * 128;
            int r = idx >> 5, c4 = (idx & 31) * 4;
            size_t goff = (size_t)(kt * BKV + r) * D_ + c4;
            *(float4*)&Ks[r * KS_STR + c4] = *(const float4*)(Kg + goff);
            *(float4*)&Vs[r * KS_STR + c4] = *(const float4*)(Vg + goff);
        }
        __syncthreads();

        // scores S = Qtile @ Ktile^T : thread does 4x4
        float s[4][4];
#pragma unroll
        for (int i = 0; i < 4; i++)
#pragma unroll
            for (int j = 0; j < 4; j++) s[i][j] = 0.0f;

#pragma unroll 8
        for (int kk = 0; kk < 32; kk++) {
            float4 qv[4], kv[4];
#pragma unroll
            for (int i = 0; i < 4; i++)
                qv[i] = *(float4*)&Qs[(rg * 4 + i) * QS_STR + kk * 4];
#pragma unroll
            for (int j = 0; j < 4; j++)
                kv[j] = *(float4*)&Ks[(cg * 4 + j) * KS_STR + kk * 4];
#pragma unroll
            for (int i = 0; i < 4; i++)
#pragma unroll
                for (int j = 0; j < 4; j++) {
                    s[i][j] += qv[i].x * kv[j].x;
                    s[i][j] += qv[i].y * kv[j].y;
                    s[i][j] += qv[i].z * kv[j].z;
                    s[i][j] += qv[i].w * kv[j].w;
                }
        }

        const int kvbase = kt * BKV;
        const bool needMask = (kt >= 2 * qb);

        // per-row online softmax
#pragma unroll
        for (int i = 0; i < 4; i++) {
            const int qidx = q0 + rg * 4 + i;
            float sv[4];
#pragma unroll
            for (int j = 0; j < 4; j++) {
                float x = s[i][j] * scale;
                if (needMask && (kvbase + cg * 4 + j > qidx)) x = -1e30f;
                sv[j] = x;
            }
            float rmax = fmaxf(fmaxf(sv[0], sv[1]), fmaxf(sv[2], sv[3]));
#pragma unroll
            for (int o = 1; o < 8; o <<= 1)
                rmax = fmaxf(rmax, __shfl_xor_sync(0xffffffffu, rmax, o));
            float mNew = fmaxf(m[i], rmax);
            float alpha = __expf(m[i] - mNew);
            float p[4], rsum = 0.0f;
#pragma unroll
            for (int j = 0; j < 4; j++) {
                p[j] = __expf(sv[j] - mNew);
                rsum += p[j];
            }
#pragma unroll
            for (int o = 1; o < 8; o <<= 1)
                rsum += __shfl_xor_sync(0xffffffffu, rsum, o);
            l[i] = l[i] * alpha + rsum;
            m[i] = mNew;
#pragma unroll
            for (int c = 0; c < 16; c++) acc[i][c] *= alpha;
#pragma unroll
            for (int j = 0; j < 4; j++)
                Ps[(rg * 4 + i) * PS_STR + cg * 4 + j] = p[j];
        }
        __syncthreads();

        // O += P @ Vtile : thread cols = cg*4 + 32*cc + w
#pragma unroll 8
        for (int kv = 0; kv < BKV; kv++) {
            float p0 = Ps[(rg * 4 + 0) * PS_STR + kv];
            float p1 = Ps[(rg * 4 + 1) * PS_STR + kv];
            float p2 = Ps[(rg * 4 + 2) * PS_STR + kv];
            float p3 = Ps[(rg * 4 + 3) * PS_STR + kv];
#pragma unroll
            for (int cc = 0; cc < 4; cc++) {
                float4 v = *(float4*)&Vs[kv * KS_STR + cg * 4 + cc * 32];
                acc[0][cc * 4 + 0] += p0 * v.x; acc[0][cc * 4 + 1] += p0 * v.y;
                acc[0][cc * 4 + 2] += p0 * v.z; acc[0][cc * 4 + 3] += p0 * v.w;
                acc[1][cc * 4 + 0] += p1 * v.x; acc[1][cc * 4 + 1] += p1 * v.y;
                acc[1][cc * 4 + 2] += p1 * v.z; acc[1][cc * 4 + 3] += p1 * v.w;
                acc[2][cc * 4 + 0] += p2 * v.x; acc[2][cc * 4 + 1] += p2 * v.y;
                acc[2][cc * 4 + 2] += p2 * v.z; acc[2][cc * 4 + 3] += p2 * v.w;
                acc[3][cc * 4 + 0] += p3 * v.x; acc[3][cc * 4 + 1] += p3 * v.y;
                acc[3][cc * 4 + 2] += p3 * v.z; acc[3][cc * 4 + 3] += p3 * v.w;
            }
        }
    }

    // finalize + write to [B,T,C] with head offset (so proj GEMM reads row-major)
#pragma unroll
    for (int i = 0; i < 4; i++) {
        float inv = 1.0f / l[i];
        const int q = q0 + rg * 4 + i;
        float* outp = g_attn + ((size_t)(b * T_ + q)) * C_ + h * D_;
#pragma unroll
        for (int cc = 0; cc < 4; cc++) {
            float4 v;
            v.x = acc[i][cc * 4 + 0] * inv;
            v.y = acc[i][cc * 4 + 1] * inv;
            v.z = acc[i][cc * 4 + 2] * inv;
            v.w = acc[i][cc * 4 + 3] * inv;
            *(float4*)(outp + cg * 4 + cc * 32) = v;
        }
    }
    (void)Out;
}

// ---------------- launch -------------------------------------------------------
extern "C" void kernel_launch(void* const* d_in, const int* in_sizes, int n_in,
                              void* d_out, int out_size)
{
    const float* x      = (const float*)d_in[0];
    const float* cosg   = (const float*)d_in[1];
    const float* sing   = (const float*)d_in[2];
    const float* W_qkv  = (const float*)d_in[3];
    const float* W_proj = (const float*)d_in[4];
    float* out = (float*)d_out;

    float* qkv;  cudaGetSymbolAddress((void**)&qkv,  g_qkv);
    float* Qb;   cudaGetSymbolAddress((void**)&Qb,   g_Q);
    float* Kb;   cudaGetSymbolAddress((void**)&Kb,   g_K);
    float* Vb;   cudaGetSymbolAddress((void**)&Vb,   g_V);
    float* attn; cudaGetSymbolAddress((void**)&attn, g_attn);

    const int M = B_ * T_;  // 4096

    // 1) qkv = x @ W_qkv   [4096,2048]@[2048,6144]
    {
        dim3 grid(3 * C_ / BN, M / BM);
        sgemm_kernel<<<grid, 256>>>(x, W_qkv, qkv, M, 3 * C_, C_);
    }

    // 2) RoPE + split into [B,H,T,D]
    {
        dim3 grid(H_, T_, B_);
        rope_split_kernel<<<grid, 128>>>(qkv, cosg, sing, Qb, Kb, Vb);
    }

    // 3) causal attention -> g_attn [B,T,C]
    {
        static int smemSet = 0;
        cudaFuncSetAttribute(attn_kernel,
                             cudaFuncAttributeMaxDynamicSharedMemorySize,
                             ATTN_SMEM_FLOATS * sizeof(float));
        (void)smemSet;
        dim3 grid(T_ / BQ, B_ * H_);
        attn_kernel<<<grid, 128, ATTN_SMEM_FLOATS * sizeof(float)>>>(Qb, Kb, Vb, attn);
    }

    // 4) out = attn @ W_proj  [4096,2048]@[2048,2048]
    {
        dim3 grid(C_ / BN, M / BM);
        sgemm_kernel<<<grid, 256>>>(attn, W_proj, out, M, C_, C_);
    }
}

// round 2
// speedup vs baseline: 1.6375x; 1.6375x over previous
#include <cuda_runtime.h>
#include <cstdio>

#define B_ 2
#define T_ 2048
#define C_ 2048
#define H_ 16
#define D_ 128

// ---------------- scratch (device globals: no runtime allocation) ----------------
__device__ float g_qkv[(size_t)B_ * T_ * 3 * C_];     // 100.7 MB
__device__ float g_Q[(size_t)B_ * H_ * T_ * D_];      // 33.5 MB
__device__ float g_K[(size_t)B_ * H_ * T_ * D_];
__device__ float g_V[(size_t)B_ * H_ * T_ * D_];
__device__ float g_attn[(size_t)B_ * T_ * C_];        // 33.5 MB

// ---------------- tf32 helpers --------------------------------------------------
__device__ __forceinline__ float to_tf32(float x) {
    unsigned u;
    asm("cvt.rna.tf32.f32 %0, %1;" : "=r"(u) : "f"(x));
    return __uint_as_float(u);
}

__device__ __forceinline__ void mma_tf32(float c[4], const float a[4], const float b[2]) {
    asm volatile(
        "mma.sync.aligned.m16n8k8.row.col.f32.tf32.tf32.f32 "
        "{%0,%1,%2,%3}, {%4,%5,%6,%7}, {%8,%9}, {%0,%1,%2,%3};"
        : "+f"(c[0]), "+f"(c[1]), "+f"(c[2]), "+f"(c[3])
        : "r"(__float_as_uint(a[0])), "r"(__float_as_uint(a[1])),
          "r"(__float_as_uint(a[2])), "r"(__float_as_uint(a[3])),
          "r"(__float_as_uint(b[0])), "r"(__float_as_uint(b[1])));
}

// ---------------- tf32 tensor-core GEMM: C[M,N]=A[M,K]@B[K,N], row-major --------
// 128x128 block tile, BK=16, 8 warps in 2(m) x 4(n), warp tile 64x32.
#define GBM 128
#define GBN 128
#define GBK 16
#define AS_STR (GBM + 4)
#define BS_STR (GBN + 4)

__global__ __launch_bounds__(256, 2) void mma_gemm_kernel(
    const float* __restrict__ A, const float* __restrict__ Bm, float* __restrict__ Cm,
    int M, int N, int K)
{
    __shared__ float As[GBK][AS_STR];   // [k][m]
    __shared__ float Bs[GBK][BS_STR];   // [k][n]

    const int tid = threadIdx.x;
    const int warp = tid >> 5;
    const int lane = tid & 31;
    const int lm = lane >> 2;   // 0..7
    const int lk = lane & 3;    // 0..3

    const int m0 = blockIdx.y * GBM;
    const int n0 = blockIdx.x * GBN;
    const int wm = (warp >> 2) * 64;   // 0 or 64
    const int wn = (warp & 3) * 32;    // 0,32,64,96

    // global load indices (per 512-float4 tile, 2 float4 per thread each)
    const int aRow = tid >> 1;            // 0..127  (m)
    const int aK4  = (tid & 1) * 8;       // 0 or 8  (two k-groups of 4 handled below)
    const int bRow = tid >> 5;            // 0..7    (k, two halves)
    const int bCol = (lane) * 4;          // 0..124  (n)

    float acc[4][4][4];
#pragma unroll
    for (int mi = 0; mi < 4; mi++)
#pragma unroll
        for (int ni = 0; ni < 4; ni++)
#pragma unroll
            for (int r = 0; r < 4; r++) acc[mi][ni][r] = 0.0f;

    const float* Ap = A + (size_t)(m0 + aRow) * K;
    const float* Bp = Bm + n0;

    for (int k0 = 0; k0 < K; k0 += GBK) {
        __syncthreads();
        // A tile: 128 x 16 -> As[k][m]; each thread: 2 float4 along k
#pragma unroll
        for (int half = 0; half < 2; half++) {
            float4 a4 = *(const float4*)(Ap + k0 + aK4 + half * 4);
            int kk = aK4 + half * 4;
            As[kk + 0][aRow] = to_tf32(a4.x);
            As[kk + 1][aRow] = to_tf32(a4.y);
            As[kk + 2][aRow] = to_tf32(a4.z);
            As[kk + 3][aRow] = to_tf32(a4.w);
        }
        // B tile: 16 x 128 -> Bs[k][n]; each thread: 2 float4 (rows bRow, bRow+8)
#pragma unroll
        for (int half = 0; half < 2; half++) {
            int kk = bRow + half * 8;
            float4 b4 = *(const float4*)(Bp + (size_t)(k0 + kk) * N + bCol);
            Bs[kk][bCol + 0] = to_tf32(b4.x);
            Bs[kk][bCol + 1] = to_tf32(b4.y);
            Bs[kk][bCol + 2] = to_tf32(b4.z);
            Bs[kk][bCol + 3] = to_tf32(b4.w);
        }
        __syncthreads();

#pragma unroll
        for (int kk = 0; kk < GBK; kk += 8) {
            float afr[4][4];
#pragma unroll
            for (int mi = 0; mi < 4; mi++) {
                int mbase = wm + mi * 16 + lm;
                afr[mi][0] = As[kk + lk][mbase];
                afr[mi][1] = As[kk + lk][mbase + 8];
                afr[mi][2] = As[kk + lk + 4][mbase];
                afr[mi][3] = As[kk + lk + 4][mbase + 8];
            }
            float bfr[4][2];
#pragma unroll
            for (int ni = 0; ni < 4; ni++) {
                int nbase = wn + ni * 8 + lm;
                bfr[ni][0] = Bs[kk + lk][nbase];
                bfr[ni][1] = Bs[kk + lk + 4][nbase];
            }
#pragma unroll
            for (int mi = 0; mi < 4; mi++)
#pragma unroll
                for (int ni = 0; ni < 4; ni++)
                    mma_tf32(acc[mi][ni], afr[mi], bfr[ni]);
        }
    }

    // epilogue: c0,c1 -> (row lm, cols 2lk,2lk+1); c2,c3 -> (row lm+8, same cols)
#pragma unroll
    for (int mi = 0; mi < 4; mi++) {
#pragma unroll
        for (int ni = 0; ni < 4; ni++) {
            int gr = m0 + wm + mi * 16 + lm;
            int gc = n0 + wn + ni * 8 + lk * 2;
            float* p0 = Cm + (size_t)gr * N + gc;
            float* p1 = Cm + (size_t)(gr + 8) * N + gc;
            *(float2*)p0 = make_float2(acc[mi][ni][0], acc[mi][ni][1]);
            *(float2*)p1 = make_float2(acc[mi][ni][2], acc[mi][ni][3]);
        }
    }
}

// ---------------- RoPE + split/transpose: qkv [B,T,3C] -> Q/K/V [B,H,T,D] -------
__global__ __launch_bounds__(128) void rope_split_kernel(
    const float* __restrict__ qkv, const float* __restrict__ cosg,
    const float* __restrict__ sing,
    float* __restrict__ Q, float* __restrict__ K, float* __restrict__ V)
{
    const int h = blockIdx.x;
    const int t = blockIdx.y;
    const int b = blockIdx.z;
    const int d = threadIdx.x;  // 0..127

    const float* base = qkv + ((size_t)(b * T_ + t)) * (3 * C_) + h * D_;
    const size_t outBase = ((size_t)((b * H_ + h) * T_ + t)) * D_;

    V[outBase + d] = base[2 * C_ + d];

    if (d < D_ / 2) {
        const float c = cosg[t * (D_ / 2) + d];
        const float s = sing[t * (D_ / 2) + d];
        float q1 = base[d];
        float q2 = base[d + D_ / 2];
        Q[outBase + d]          = q1 * c - q2 * s;
        Q[outBase + d + D_ / 2] = q1 * s + q2 * c;
        float k1 = base[C_ + d];
        float k2 = base[C_ + d + D_ / 2];
        K[outBase + d]          = k1 * c - k2 * s;
        K[outBase + d + D_ / 2] = k1 * s + k2 * c;
    }
}

// ---------------- causal flash attention, fp32 ---------------------------------
#define BQ 64
#define BKV 32
#define QS_STR 132
#define KS_STR 132
#define PS_STR 33
#define ATTN_SMEM_FLOATS (64 * QS_STR + 32 * KS_STR + 32 * KS_STR + 64 * PS_STR)

__global__ __launch_bounds__(128) void attn_kernel(
    const float* __restrict__ Q, const float* __restrict__ K,
    const float* __restrict__ V, float* __restrict__ Out)
{
    extern __shared__ float smem[];
    float* Qs = smem;
    float* Ks = Qs + 64 * QS_STR;
    float* Vs = Ks + 32 * KS_STR;
    float* Ps = Vs + 32 * KS_STR;

    const int qb = blockIdx.x;
    const int bh = blockIdx.y;
    const int b = bh / H_;
    const int h = bh % H_;
    const int tid = threadIdx.x;
    const int rg = tid >> 3;
    const int cg = tid & 7;
    const int q0 = qb * BQ;

    const float* Qg = Q + ((size_t)bh * T_ + q0) * D_;
    const float* Kg = K + (size_t)bh * T_ * D_;
    const float* Vg = V + (size_t)bh * T_ * D_;

#pragma unroll
    for (int i = 0; i < 16; i++) {
        int idx = tid + i * 128;
        int r = idx >> 5, c4 = (idx & 31) * 4;
        *(float4*)&Qs[r * QS_STR + c4] = *(const float4*)(Qg + (size_t)r * D_ + c4);
    }

    float m[4], l[4], acc[4][16];
#pragma unroll
    for (int i = 0; i < 4; i++) {
        m[i] = -1e30f;
        l[i] = 0.0f;
#pragma unroll
        for (int c = 0; c < 16; c++) acc[i][c] = 0.0f;
    }

    const float scale = 0.08838834764831845f;
    const int nkv = (q0 + BQ) / BKV;

    for (int kt = 0; kt < nkv; kt++) {
        __syncthreads();
#pragma unroll
        for (int i = 0; i < 8; i++) {
            int idx = tid + i * 128;
            int r = idx >> 5, c4 = (idx & 31) * 4;
            size_t goff = (size_t)(kt * BKV + r) * D_ + c4;
            *(float4*)&Ks[r * KS_STR + c4] = *(const float4*)(Kg + goff);
            *(float4*)&Vs[r * KS_STR + c4] = *(const float4*)(Vg + goff);
        }
        __syncthreads();

        float s[4][4];
#pragma unroll
        for (int i = 0; i < 4; i++)
#pragma unroll
            for (int j = 0; j < 4; j++) s[i][j] = 0.0f;

#pragma unroll 8
        for (int kk = 0; kk < 32; kk++) {
            float4 qv[4], kv[4];
#pragma unroll
            for (int i = 0; i < 4; i++)
                qv[i] = *(float4*)&Qs[(rg * 4 + i) * QS_STR + kk * 4];
#pragma unroll
            for (int j = 0; j < 4; j++)
                kv[j] = *(float4*)&Ks[(cg * 4 + j) * KS_STR + kk * 4];
#pragma unroll
            for (int i = 0; i < 4; i++)
#pragma unroll
                for (int j = 0; j < 4; j++) {
                    s[i][j] += qv[i].x * kv[j].x;
                    s[i][j] += qv[i].y * kv[j].y;
                    s[i][j] += qv[i].z * kv[j].z;
                    s[i][j] += qv[i].w * kv[j].w;
                }
        }

        const int kvbase = kt * BKV;
        const bool needMask = (kt >= 2 * qb);

#pragma unroll
        for (int i = 0; i < 4; i++) {
            const int qidx = q0 + rg * 4 + i;
            float sv[4];
#pragma unroll
            for (int j = 0; j < 4; j++) {
                float x = s[i][j] * scale;
                if (needMask && (kvbase + cg * 4 + j > qidx)) x = -1e30f;
                sv[j] = x;
            }
            float rmax = fmaxf(fmaxf(sv[0], sv[1]), fmaxf(sv[2], sv[3]));
#pragma unroll
            for (int o = 1; o < 8; o <<= 1)
                rmax = fmaxf(rmax, __shfl_xor_sync(0xffffffffu, rmax, o));
            float mNew = fmaxf(m[i], rmax);
            float alpha = __expf(m[i] - mNew);
            float p[4], rsum = 0.0f;
#pragma unroll
            for (int j = 0; j < 4; j++) {
                p[j] = __expf(sv[j] - mNew);
                rsum += p[j];
            }
#pragma unroll
            for (int o = 1; o < 8; o <<= 1)
                rsum += __shfl_xor_sync(0xffffffffu, rsum, o);
            l[i] = l[i] * alpha + rsum;
            m[i] = mNew;
#pragma unroll
            for (int c = 0; c < 16; c++) acc[i][c] *= alpha;
#pragma unroll
            for (int j = 0; j < 4; j++)
                Ps[(rg * 4 + i) * PS_STR + cg * 4 + j] = p[j];
        }
        __syncthreads();

#pragma unroll 8
        for (int kv = 0; kv < BKV; kv++) {
            float p0 = Ps[(rg * 4 + 0) * PS_STR + kv];
            float p1 = Ps[(rg * 4 + 1) * PS_STR + kv];
            float p2 = Ps[(rg * 4 + 2) * PS_STR + kv];
            float p3 = Ps[(rg * 4 + 3) * PS_STR + kv];
#pragma unroll
            for (int cc = 0; cc < 4; cc++) {
                float4 v = *(float4*)&Vs[kv * KS_STR + cg * 4 + cc * 32];
                acc[0][cc * 4 + 0] += p0 * v.x; acc[0][cc * 4 + 1] += p0 * v.y;
                acc[0][cc * 4 + 2] += p0 * v.z; acc[0][cc * 4 + 3] += p0 * v.w;
                acc[1][cc * 4 + 0] += p1 * v.x; acc[1][cc * 4 + 1] += p1 * v.y;
                acc[1][cc * 4 + 2] += p1 * v.z; acc[1][cc * 4 + 3] += p1 * v.w;
                acc[2][cc * 4 + 0] += p2 * v.x; acc[2][cc * 4 + 1] += p2 * v.y;
                acc[2][cc * 4 + 2] += p2 * v.z; acc[2][cc * 4 + 3] += p2 * v.w;
                acc[3][cc * 4 + 0] += p3 * v.x; acc[3][cc * 4 + 1] += p3 * v.y;
                acc[3][cc * 4 + 2] += p3 * v.z; acc[3][cc * 4 + 3] += p3 * v.w;
            }
        }
    }

#pragma unroll
    for (int i = 0; i < 4; i++) {
        float inv = 1.0f / l[i];
        const int q = q0 + rg * 4 + i;
        float* outp = g_attn + ((size_t)(b * T_ + q)) * C_ + h * D_;
#pragma unroll
        for (int cc = 0; cc < 4; cc++) {
            float4 v;
            v.x = acc[i][cc * 4 + 0] * inv;
            v.y = acc[i][cc * 4 + 1] * inv;
            v.z = acc[i][cc * 4 + 2] * inv;
            v.w = acc[i][cc * 4 + 3] * inv;
            *(float4*)(outp + cg * 4 + cc * 32) = v;
        }
    }
    (void)Out;
}

// ---------------- launch -------------------------------------------------------
extern "C" void kernel_launch(void* const* d_in, const int* in_sizes, int n_in,
                              void* d_out, int out_size)
{
    const float* x      = (const float*)d_in[0];
    const float* cosg   = (const float*)d_in[1];
    const float* sing   = (const float*)d_in[2];
    const float* W_qkv  = (const float*)d_in[3];
    const float* W_proj = (const float*)d_in[4];
    float* out = (float*)d_out;

    float* qkv;  cudaGetSymbolAddress((void**)&qkv,  g_qkv);
    float* Qb;   cudaGetSymbolAddress((void**)&Qb,   g_Q);
    float* Kb;   cudaGetSymbolAddress((void**)&Kb,   g_K);
    float* Vb;   cudaGetSymbolAddress((void**)&Vb,   g_V);
    float* attn; cudaGetSymbolAddress((void**)&attn, g_attn);

    const int M = B_ * T_;  // 4096

    // 1) qkv = x @ W_qkv   [4096,2048]@[2048,6144]  (tf32 tensor cores)
    {
        dim3 grid(3 * C_ / GBN, M / GBM);
        mma_gemm_kernel<<<grid, 256>>>(x, W_qkv, qkv, M, 3 * C_, C_);
    }

    // 2) RoPE + split into [B,H,T,D]
    {
        dim3 grid(H_, T_, B_);
        rope_split_kernel<<<grid, 128>>>(qkv, cosg, sing, Qb, Kb, Vb);
    }

    // 3) causal attention -> g_attn [B,T,C]
    {
        cudaFuncSetAttribute(attn_kernel,
                             cudaFuncAttributeMaxDynamicSharedMemorySize,
                             ATTN_SMEM_FLOATS * sizeof(float));
        dim3 grid(T_ / BQ, B_ * H_);
        attn_kernel<<<grid, 128, ATTN_SMEM_FLOATS * sizeof(float)>>>(Qb, Kb, Vb, attn);
    }

    // 4) out = attn @ W_proj  [4096,2048]@[2048,2048]  (tf32 tensor cores)
    {
        dim3 grid(C_ / GBN, M / GBM);
        mma_gemm_kernel<<<grid, 256>>>(attn, W_proj, out, M, C_, C_);
    }
}

// round 3
// speedup vs baseline: 3.4032x; 2.0783x over previous
#include <cuda_runtime.h>
#include <cstdio>

#define B_ 2
#define T_ 2048
#define C_ 2048
#define H_ 16
#define D_ 128

// ---------------- scratch (device globals: no runtime allocation) ----------------
__device__ float g_qkv[(size_t)B_ * T_ * 3 * C_];
__device__ float g_Q[(size_t)B_ * H_ * T_ * D_];
__device__ float g_K[(size_t)B_ * H_ * T_ * D_];
__device__ float g_V[(size_t)B_ * H_ * T_ * D_];
__device__ float g_attn[(size_t)B_ * T_ * C_];

// ---------------- tf32 helpers --------------------------------------------------
__device__ __forceinline__ float to_tf32(float x) {
    unsigned u;
    asm("cvt.rna.tf32.f32 %0, %1;" : "=r"(u) : "f"(x));
    return __uint_as_float(u);
}

__device__ __forceinline__ void mma_tf32(float c[4], const float a[4], const float b[2]) {
    asm volatile(
        "mma.sync.aligned.m16n8k8.row.col.f32.tf32.tf32.f32 "
        "{%0,%1,%2,%3}, {%4,%5,%6,%7}, {%8,%9}, {%0,%1,%2,%3};"
        : "+f"(c[0]), "+f"(c[1]), "+f"(c[2]), "+f"(c[3])
        : "r"(__float_as_uint(a[0])), "r"(__float_as_uint(a[1])),
          "r"(__float_as_uint(a[2])), "r"(__float_as_uint(a[3])),
          "r"(__float_as_uint(b[0])), "r"(__float_as_uint(b[1])));
}

// ---------------- tf32 tensor-core GEMM (conflict-free strides) -----------------
#define GBM 128
#define GBN 128
#define GBK 16
#define AS_STR (GBM + 8)
#define BS_STR (GBN + 8)

__global__ __launch_bounds__(256, 2) void mma_gemm_kernel(
    const float* __restrict__ A, const float* __restrict__ Bm, float* __restrict__ Cm,
    int M, int N, int K)
{
    __shared__ float As[GBK][AS_STR];   // [k][m]
    __shared__ float Bs[GBK][BS_STR];   // [k][n]

    const int tid = threadIdx.x;
    const int warp = tid >> 5;
    const int lane = tid & 31;
    const int lm = lane >> 2;
    const int lk = lane & 3;

    const int m0 = blockIdx.y * GBM;
    const int n0 = blockIdx.x * GBN;
    const int wm = (warp >> 2) * 64;
    const int wn = (warp & 3) * 32;

    const int aRow = tid >> 1;
    const int aK4  = (tid & 1) * 8;
    const int bRow = tid >> 5;
    const int bCol = lane * 4;

    float acc[4][4][4];
#pragma unroll
    for (int mi = 0; mi < 4; mi++)
#pragma unroll
        for (int ni = 0; ni < 4; ni++)
#pragma unroll
            for (int r = 0; r < 4; r++) acc[mi][ni][r] = 0.0f;

    const float* Ap = A + (size_t)(m0 + aRow) * K;
    const float* Bp = Bm + n0;

    for (int k0 = 0; k0 < K; k0 += GBK) {
        __syncthreads();
#pragma unroll
        for (int half = 0; half < 2; half++) {
            float4 a4 = *(const float4*)(Ap + k0 + aK4 + half * 4);
            int kk = aK4 + half * 4;
            As[kk + 0][aRow] = to_tf32(a4.x);
            As[kk + 1][aRow] = to_tf32(a4.y);
            As[kk + 2][aRow] = to_tf32(a4.z);
            As[kk + 3][aRow] = to_tf32(a4.w);
        }
#pragma unroll
        for (int half = 0; half < 2; half++) {
            int kk = bRow + half * 8;
            float4 b4 = *(const float4*)(Bp + (size_t)(k0 + kk) * N + bCol);
            b4.x = to_tf32(b4.x); b4.y = to_tf32(b4.y);
            b4.z = to_tf32(b4.z); b4.w = to_tf32(b4.w);
            *(float4*)&Bs[kk][bCol] = b4;
        }
        __syncthreads();

#pragma unroll
        for (int kk = 0; kk < GBK; kk += 8) {
            float afr[4][4];
#pragma unroll
            for (int mi = 0; mi < 4; mi++) {
                int mbase = wm + mi * 16 + lm;
                afr[mi][0] = As[kk + lk][mbase];
                afr[mi][1] = As[kk + lk][mbase + 8];
                afr[mi][2] = As[kk + lk + 4][mbase];
                afr[mi][3] = As[kk + lk + 4][mbase + 8];
            }
            float bfr[4][2];
#pragma unroll
            for (int ni = 0; ni < 4; ni++) {
                int nbase = wn + ni * 8 + lm;
                bfr[ni][0] = Bs[kk + lk][nbase];
                bfr[ni][1] = Bs[kk + lk + 4][nbase];
            }
#pragma unroll
            for (int mi = 0; mi < 4; mi++)
#pragma unroll
                for (int ni = 0; ni < 4; ni++)
                    mma_tf32(acc[mi][ni], afr[mi], bfr[ni]);
        }
    }

#pragma unroll
    for (int mi = 0; mi < 4; mi++) {
#pragma unroll
        for (int ni = 0; ni < 4; ni++) {
            int gr = m0 + wm + mi * 16 + lm;
            int gc = n0 + wn + ni * 8 + lk * 2;
            float* p0 = Cm + (size_t)gr * N + gc;
            float* p1 = Cm + (size_t)(gr + 8) * N + gc;
            *(float2*)p0 = make_float2(acc[mi][ni][0], acc[mi][ni][1]);
            *(float2*)p1 = make_float2(acc[mi][ni][2], acc[mi][ni][3]);
        }
    }
}

// ---------------- RoPE + split/transpose ----------------------------------------
__global__ __launch_bounds__(128) void rope_split_kernel(
    const float* __restrict__ qkv, const float* __restrict__ cosg,
    const float* __restrict__ sing,
    float* __restrict__ Q, float* __restrict__ K, float* __restrict__ V)
{
    const int h = blockIdx.x;
    const int t = blockIdx.y;
    const int b = blockIdx.z;
    const int d = threadIdx.x;

    const float* base = qkv + ((size_t)(b * T_ + t)) * (3 * C_) + h * D_;
    const size_t outBase = ((size_t)((b * H_ + h) * T_ + t)) * D_;

    V[outBase + d] = base[2 * C_ + d];

    if (d < D_ / 2) {
        const float c = cosg[t * (D_ / 2) + d];
        const float s = sing[t * (D_ / 2) + d];
        float q1 = base[d];
        float q2 = base[d + D_ / 2];
        Q[outBase + d]          = q1 * c - q2 * s;
        Q[outBase + d + D_ / 2] = q1 * s + q2 * c;
        float k1 = base[C_ + d];
        float k2 = base[C_ + d + D_ / 2];
        K[outBase + d]          = k1 * c - k2 * s;
        K[outBase + d + D_ / 2] = k1 * s + k2 * c;
    }
}

// ---------------- tf32 MMA flash attention --------------------------------------
// BQ=64 (4 warps x m16), BKV=32, D=128. Fragment-ready smem layouts:
//  Qs: A-frag tiles [rt(4)][kt(16)], tile stride 132 floats, elem at lane*4+reg
//  Ks: B-frag tiles [ni(4)][kt(16)], tile stride 68,  elem at lane*2+reg
//  Vs: B-frag tiles [kt2(4)][ni(16)], tile stride 68
//  Ps: A-frag tiles [w(4)][kt2(4)],   tile stride 132 (per-warp private)
#define QS_FLOATS (64 * 132)
#define KS_FLOATS (64 * 68)
#define VS_FLOATS (64 * 68)
#define PS_FLOATS (16 * 132)
#define ATTN_SMEM_FLOATS (QS_FLOATS + KS_FLOATS + VS_FLOATS + PS_FLOATS)

__global__ __launch_bounds__(128, 2) void attn_mma_kernel(
    const float* __restrict__ Q, const float* __restrict__ K,
    const float* __restrict__ V)
{
    extern __shared__ float sm[];
    float* Qs = sm;
    float* Ks = Qs + QS_FLOATS;
    float* Vs = Ks + KS_FLOATS;
    float* Ps = Vs + VS_FLOATS;

    const int qb = blockIdx.x;
    const int bh = blockIdx.y;
    const int b = bh >> 4;
    const int h = bh & 15;
    const int tid = threadIdx.x;
    const int w = tid >> 5;
    const int lane = tid & 31;
    const int lm = lane >> 2;
    const int lk = lane & 3;
    const int q0 = qb * 64;

    const float* Qg = Q + ((size_t)bh * T_ + q0) * D_;
    const float* Kg = K + (size_t)bh * T_ * D_;
    const float* Vg = V + (size_t)bh * T_ * D_;

    // ---- load Q tile (64x128) into A-fragment layout, tf32-rounded ----
#pragma unroll
    for (int it = 0; it < 16; it++) {
        int idx = tid + it * 128;
        int r = idx >> 5;
        int c4 = (idx & 31) * 4;
        float4 q4 = *(const float4*)(Qg + (size_t)r * D_ + c4);
        int kt = c4 >> 3;
        int rh = ((c4 & 7) >= 4) ? 2 : 0;
        int rb = ((r & 15) >= 8) ? 1 : 0;
        float* tp = &Qs[((r >> 4) * 16 + kt) * 132 + rh + rb];
        int lf = (r & 7) << 2;
        tp[(lf + 0) * 4] = to_tf32(q4.x);
        tp[(lf + 1) * 4] = to_tf32(q4.y);
        tp[(lf + 2) * 4] = to_tf32(q4.z);
        tp[(lf + 3) * 4] = to_tf32(q4.w);
    }

    float m0 = -1e30f, m1 = -1e30f, l0 = 0.0f, l1 = 0.0f;
    float oacc[16][4];
#pragma unroll
    for (int ni = 0; ni < 16; ni++)
#pragma unroll
        for (int r = 0; r < 4; r++) oacc[ni][r] = 0.0f;

    const float scale = 0.08838834764831845f;  // 1/sqrt(128)
    const int nkv = (q0 + 64) / 32;
    const int row0g = q0 + w * 16 + lm;
    const int row1g = row0g + 8;

    for (int kt = 0; kt < nkv; kt++) {
        const int kv0 = kt * 32;
        __syncthreads();
        // ---- load K,V tiles (32x128) into B-fragment layouts ----
#pragma unroll
        for (int it = 0; it < 8; it++) {
            int idx = tid + it * 128;
            int r = idx >> 5;
            int c4 = (idx & 31) * 4;
            size_t goff = (size_t)(kv0 + r) * D_ + c4;
            float4 k4 = *(const float4*)(Kg + goff);
            float4 v4 = *(const float4*)(Vg + goff);
            int dkt = c4 >> 3;
            int rhK = ((c4 & 7) >= 4) ? 1 : 0;
            // K: tile [ni=r>>3][kt=dkt], lane = 4*(r&7) + (d&3), reg = rhK
            {
                float* tp = &Ks[((r >> 3) * 16 + dkt) * 68 + rhK];
                int lf = (r & 7) << 2;
                tp[(lf + 0) * 2] = to_tf32(k4.x);
                tp[(lf + 1) * 2] = to_tf32(k4.y);
                tp[(lf + 2) * 2] = to_tf32(k4.z);
                tp[(lf + 3) * 2] = to_tf32(k4.w);
            }
            // V: tile [kt2=r>>3][ni=dkt], lane = 4*(d&7) + (kv&3), reg = (r&7)>=4
            {
                int rhV = ((r & 7) >= 4) ? 1 : 0;
                float* tp = &Vs[((r >> 3) * 16 + dkt) * 68 + rhV];
                int dbase = c4 & 7;
                int kl = r & 3;
                tp[((dbase + 0) * 4 + kl) * 2] = to_tf32(v4.x);
                tp[((dbase + 1) * 4 + kl) * 2] = to_tf32(v4.y);
                tp[((dbase + 2) * 4 + kl) * 2] = to_tf32(v4.z);
                tp[((dbase + 3) * 4 + kl) * 2] = to_tf32(v4.w);
            }
        }
        __syncthreads();

        // ---- S = Q @ K^T for this warp's 16 rows ----
        float sacc[4][4];
#pragma unroll
        for (int ni = 0; ni < 4; ni++)
#pragma unroll
            for (int r = 0; r < 4; r++) sacc[ni][r] = 0.0f;

#pragma unroll
        for (int dk = 0; dk < 16; dk++) {
            float afr[4];
            *(float4*)afr = *(float4*)&Qs[(w * 16 + dk) * 132 + lane * 4];
#pragma unroll
            for (int ni = 0; ni < 4; ni++) {
                float bfr[2];
                *(float2*)bfr = *(float2*)&Ks[(ni * 16 + dk) * 68 + lane * 2];
                mma_tf32(sacc[ni], afr, bfr);
            }
        }

        // ---- scale + causal mask ----
        const bool needMask = (kt >= 2 * qb);
#pragma unroll
        for (int ni = 0; ni < 4; ni++) {
            int c0 = kv0 + ni * 8 + 2 * lk;
#pragma unroll
            for (int r = 0; r < 4; r++) sacc[ni][r] *= scale;
            if (needMask) {
                if (c0     > row0g) sacc[ni][0] = -1e30f;
                if (c0 + 1 > row0g) sacc[ni][1] = -1e30f;
                if (c0     > row1g) sacc[ni][2] = -1e30f;
                if (c0 + 1 > row1g) sacc[ni][3] = -1e30f;
            }
        }

        // ---- online softmax (rows lm and lm+8) ----
        float rmax0 = -1e30f, rmax1 = -1e30f;
#pragma unroll
        for (int ni = 0; ni < 4; ni++) {
            rmax0 = fmaxf(rmax0, fmaxf(sacc[ni][0], sacc[ni][1]));
            rmax1 = fmaxf(rmax1, fmaxf(sacc[ni][2], sacc[ni][3]));
        }
        rmax0 = fmaxf(rmax0, __shfl_xor_sync(0xffffffffu, rmax0, 1));
        rmax0 = fmaxf(rmax0, __shfl_xor_sync(0xffffffffu, rmax0, 2));
        rmax1 = fmaxf(rmax1, __shfl_xor_sync(0xffffffffu, rmax1, 1));
        rmax1 = fmaxf(rmax1, __shfl_xor_sync(0xffffffffu, rmax1, 2));
        float mn0 = fmaxf(m0, rmax0);
        float mn1 = fmaxf(m1, rmax1);
        float al0 = __expf(m0 - mn0);
        float al1 = __expf(m1 - mn1);
        float rs0 = 0.0f, rs1 = 0.0f;
#pragma unroll
        for (int ni = 0; ni < 4; ni++) {
            sacc[ni][0] = __expf(sacc[ni][0] - mn0);
            sacc[ni][1] = __expf(sacc[ni][1] - mn0);
            sacc[ni][2] = __expf(sacc[ni][2] - mn1);
            sacc[ni][3] = __expf(sacc[ni][3] - mn1);
            rs0 += sacc[ni][0] + sacc[ni][1];
            rs1 += sacc[ni][2] + sacc[ni][3];
        }
        rs0 += __shfl_xor_sync(0xffffffffu, rs0, 1);
        rs0 += __shfl_xor_sync(0xffffffffu, rs0, 2);
        rs1 += __shfl_xor_sync(0xffffffffu, rs1, 1);
        rs1 += __shfl_xor_sync(0xffffffffu, rs1, 2);
        l0 = l0 * al0 + rs0;
        l1 = l1 * al1 + rs1;
        m0 = mn0;
        m1 = mn1;
#pragma unroll
        for (int ni = 0; ni < 16; ni++) {
            oacc[ni][0] *= al0; oacc[ni][1] *= al0;
            oacc[ni][2] *= al1; oacc[ni][3] *= al1;
        }

        // ---- store P into per-warp A-fragment layout ----
#pragma unroll
        for (int ni = 0; ni < 4; ni++) {
            float* tp = &Ps[(w * 4 + ni) * 132];
            int c0 = 2 * lk;
            int lf0 = (lm << 2) | (c0 & 3);
            int rh0 = (c0 >= 4) ? 2 : 0;
            tp[lf0 * 4 + rh0]     = to_tf32(sacc[ni][0]);
            tp[lf0 * 4 + rh0 + 1] = to_tf32(sacc[ni][2]);
            int c1 = 2 * lk + 1;
            int lf1 = (lm << 2) | (c1 & 3);
            int rh1 = (c1 >= 4) ? 2 : 0;
            tp[lf1 * 4 + rh1]     = to_tf32(sacc[ni][1]);
            tp[lf1 * 4 + rh1 + 1] = to_tf32(sacc[ni][3]);
        }
        __syncwarp();

        // ---- O += P @ V ----
#pragma unroll
        for (int kt2 = 0; kt2 < 4; kt2++) {
            float afr[4];
            *(float4*)afr = *(float4*)&Ps[(w * 4 + kt2) * 132 + lane * 4];
#pragma unroll
            for (int ni = 0; ni < 16; ni++) {
                float bfr[2];
                *(float2*)bfr = *(float2*)&Vs[(kt2 * 16 + ni) * 68 + lane * 2];
                mma_tf32(oacc[ni], afr, bfr);
            }
        }
    }

    // ---- finalize + write [B,T,C] with head offset ----
    float inv0 = 1.0f / l0;
    float inv1 = 1.0f / l1;
    float* out0 = g_attn + ((size_t)(b * T_ + row0g)) * C_ + h * D_;
    float* out1 = g_attn + ((size_t)(b * T_ + row1g)) * C_ + h * D_;
#pragma unroll
    for (int ni = 0; ni < 16; ni++) {
        int col = ni * 8 + 2 * lk;
        *(float2*)(out0 + col) = make_float2(oacc[ni][0] * inv0, oacc[ni][1] * inv0);
        *(float2*)(out1 + col) = make_float2(oacc[ni][2] * inv1, oacc[ni][3] * inv1);
    }
}

// ---------------- launch -------------------------------------------------------
extern "C" void kernel_launch(void* const* d_in, const int* in_sizes, int n_in,
                              void* d_out, int out_size)
{
    const float* x      = (const float*)d_in[0];
    const float* cosg   = (const float*)d_in[1];
    const float* sing   = (const float*)d_in[2];
    const float* W_qkv  = (const float*)d_in[3];
    const float* W_proj = (const float*)d_in[4];
    float* out = (float*)d_out;

    float* qkv;  cudaGetSymbolAddress((void**)&qkv,  g_qkv);
    float* Qb;   cudaGetSymbolAddress((void**)&Qb,   g_Q);
    float* Kb;   cudaGetSymbolAddress((void**)&Kb,   g_K);
    float* Vb;   cudaGetSymbolAddress((void**)&Vb,   g_V);
    float* attn; cudaGetSymbolAddress((void**)&attn, g_attn);

    const int M = B_ * T_;

    {
        dim3 grid(3 * C_ / GBN, M / GBM);
        mma_gemm_kernel<<<grid, 256>>>(x, W_qkv, qkv, M, 3 * C_, C_);
    }
    {
        dim3 grid(H_, T_, B_);
        rope_split_kernel<<<grid, 128>>>(qkv, cosg, sing, Qb, Kb, Vb);
    }
    {
        cudaFuncSetAttribute(attn_mma_kernel,
                             cudaFuncAttributeMaxDynamicSharedMemorySize,
                             ATTN_SMEM_FLOATS * sizeof(float));
        dim3 grid(T_ / 64, B_ * H_);
        attn_mma_kernel<<<grid, 128, ATTN_SMEM_FLOATS * sizeof(float)>>>(Qb, Kb, Vb);
    }
    {
        dim3 grid(C_ / GBN, M / GBM);
        mma_gemm_kernel<<<grid, 256>>>(attn, W_proj, out, M, C_, C_);
    }
}

// round 4
// speedup vs baseline: 3.5457x; 1.0419x over previous
#include <cuda_runtime.h>
#include <cstdio>

#define B_ 2
#define T_ 2048
#define C_ 2048
#define H_ 16
#define D_ 128

// ---------------- scratch (device globals: no runtime allocation) ----------------
__device__ float g_qkv[(size_t)B_ * T_ * 3 * C_];
__device__ float g_Q[(size_t)B_ * H_ * T_ * D_];
__device__ float g_K[(size_t)B_ * H_ * T_ * D_];
__device__ float g_V[(size_t)B_ * H_ * T_ * D_];
__device__ float g_attn[(size_t)B_ * T_ * C_];

// ---------------- tf32 helpers --------------------------------------------------
__device__ __forceinline__ float to_tf32(float x) {
    unsigned u;
    asm("cvt.rna.tf32.f32 %0, %1;" : "=r"(u) : "f"(x));
    return __uint_as_float(u);
}

__device__ __forceinline__ void mma_tf32(float c[4], const float a[4], const float b[2]) {
    asm volatile(
        "mma.sync.aligned.m16n8k8.row.col.f32.tf32.tf32.f32 "
        "{%0,%1,%2,%3}, {%4,%5,%6,%7}, {%8,%9}, {%0,%1,%2,%3};"
        : "+f"(c[0]), "+f"(c[1]), "+f"(c[2]), "+f"(c[3])
        : "r"(__float_as_uint(a[0])), "r"(__float_as_uint(a[1])),
          "r"(__float_as_uint(a[2])), "r"(__float_as_uint(a[3])),
          "r"(__float_as_uint(b[0])), "r"(__float_as_uint(b[1])));
}

// ================= GEMM v2: 128x256 block, 8 warps, warp 64x64, BK=16 ==========
// Fragment-ready smem:
//  A sub-tiles: 64 floats (stride 66), sub = ((mt*2+kt)*2 + h), mt 0..7, kt 0..1,
//    h = k-half; element (r=m&7, c=k&3, rb=(m>>3)&1) at offset (r*4+c)*2 + rb.
//  B tiles: 64 floats (stride 66), tile = nt*2+kt, nt 0..31; element
//    (n&7, k&3, rg=(k>>2)&1) at ((n&7)*4+(k&3))*2 + rg.
// Compute: A-frag = 2x LDS.64, B-frag = 1x LDS.64 (contiguous, conflict-free).
#define GBM 128
#define GBN 256
#define GBK 16
#define SUB_STR 66
#define A_BUF (32 * SUB_STR)           // 2112 floats
#define B_BUF (64 * SUB_STR)           // 4224 floats
#define GEMM_SMEM_FLOATS (2 * (A_BUF + B_BUF))  // 12672 floats = 50688 B

__global__ __launch_bounds__(256, 1) void mma_gemm2_kernel(
    const float* __restrict__ A, const float* __restrict__ Bm, float* __restrict__ Cm,
    int M, int N, int K)
{
    extern __shared__ float sm[];
    // [A0][A1][B0][B1]
    const int tid = threadIdx.x;
    const int warp = tid >> 5;
    const int lane = tid & 31;
    const int lm = lane >> 2;
    const int lk = lane & 3;

    const int m0 = blockIdx.y * GBM;
    const int n0 = blockIdx.x * GBN;
    const int wmt = (warp >> 2) * 4;   // A tile base (mt), 0 or 4
    const int wnt = (warp & 3) * 8;    // B tile base (nt)

    // loader indices
    const int aRow = tid >> 1;         // 0..127
    const int akt = tid & 1;           // k-tile 0/1
    const int bk = tid >> 4;           // 0..15
    const int bn4 = (tid & 15) * 4;    // 0..60

    const float* Ag = A + (size_t)(m0 + aRow) * K + akt * 8;
    const float* Bg = Bm + (size_t)bk * N + n0 + bn4;

    // precomputed STS offsets
    const int aSubBase = ((aRow >> 4) * 2 + akt) * 2;           // + h
    const int aOffBase = (aRow & 7) * 8 + ((aRow >> 3) & 1);    // + j*2
    const int bTileB = (bk >> 3);                                // + (n4>>3)*2
    const int bOffBase = (bk & 3) * 2 + ((bk >> 2) & 1);        // + ((n4&7)+j)*8

    float acc[4][8][4];
#pragma unroll
    for (int mi = 0; mi < 4; mi++)
#pragma unroll
        for (int ni = 0; ni < 8; ni++)
#pragma unroll
            for (int r = 0; r < 4; r++) acc[mi][ni][r] = 0.0f;

    float4 aS[2], bS[4];

    // ---- prologue: load + store slab 0 ----
#pragma unroll
    for (int h = 0; h < 2; h++) aS[h] = *(const float4*)(Ag + h * 4);
#pragma unroll
    for (int it = 0; it < 4; it++) bS[it] = *(const float4*)(Bg + it * 64);

    {
        float* Ab = sm;           // buffer 0
        float* Bb = sm + 2 * A_BUF;
#pragma unroll
        for (int h = 0; h < 2; h++) {
            float* tp = Ab + (aSubBase + h) * SUB_STR + aOffBase;
            tp[0] = to_tf32(aS[h].x); tp[2] = to_tf32(aS[h].y);
            tp[4] = to_tf32(aS[h].z); tp[6] = to_tf32(aS[h].w);
        }
#pragma unroll
        for (int it = 0; it < 4; it++) {
            int n4 = bn4 + it * 64;
            float* tp = Bb + ((n4 >> 3) * 2 + bTileB) * SUB_STR + ((n4 & 7) * 8) + bOffBase;
            tp[0]  = to_tf32(bS[it].x); tp[8]  = to_tf32(bS[it].y);
            tp[16] = to_tf32(bS[it].z); tp[24] = to_tf32(bS[it].w);
        }
    }
    __syncthreads();

    const int nslab = K / GBK;
    for (int s = 0; s < nslab; s++) {
        const int cur = s & 1;
        const bool more = (s + 1 < nslab);
        if (more) {
            const int k1 = (s + 1) * GBK;
#pragma unroll
            for (int h = 0; h < 2; h++) aS[h] = *(const float4*)(Ag + k1 + h * 4);
#pragma unroll
            for (int it = 0; it < 4; it++)
                bS[it] = *(const float4*)(Bg + (size_t)k1 * N + it * 64);
        }

        const float* Ab = sm + cur * A_BUF;
        const float* Bb = sm + 2 * A_BUF + cur * B_BUF;

#pragma unroll
        for (int kk = 0; kk < 2; kk++) {
            float afr[4][4];
#pragma unroll
            for (int mi = 0; mi < 4; mi++) {
                int sub = ((wmt + mi) * 2 + kk) * 2;
                *(float2*)&afr[mi][0] = *(const float2*)&Ab[sub * SUB_STR + lane * 2];
                *(float2*)&afr[mi][2] = *(const float2*)&Ab[(sub + 1) * SUB_STR + lane * 2];
            }
            float bfr[8][2];
#pragma unroll
            for (int ni = 0; ni < 8; ni++)
                *(float2*)bfr[ni] = *(const float2*)&Bb[((wnt + ni) * 2 + kk) * SUB_STR + lane * 2];
#pragma unroll
            for (int mi = 0; mi < 4; mi++)
#pragma unroll
                for (int ni = 0; ni < 8; ni++)
                    mma_tf32(acc[mi][ni], afr[mi], bfr[ni]);
        }

        if (more) {
            float* Abn = sm + (cur ^ 1) * A_BUF;
            float* Bbn = sm + 2 * A_BUF + (cur ^ 1) * B_BUF;
#pragma unroll
            for (int h = 0; h < 2; h++) {
                float* tp = Abn + (aSubBase + h) * SUB_STR + aOffBase;
                tp[0] = to_tf32(aS[h].x); tp[2] = to_tf32(aS[h].y);
                tp[4] = to_tf32(aS[h].z); tp[6] = to_tf32(aS[h].w);
            }
#pragma unroll
            for (int it = 0; it < 4; it++) {
                int n4 = bn4 + it * 64;
                float* tp = Bbn + ((n4 >> 3) * 2 + bTileB) * SUB_STR + ((n4 & 7) * 8) + bOffBase;
                tp[0]  = to_tf32(bS[it].x); tp[8]  = to_tf32(bS[it].y);
                tp[16] = to_tf32(bS[it].z); tp[24] = to_tf32(bS[it].w);
            }
            __syncthreads();
        }
    }

    // ---- epilogue ----
    const int wm = (warp >> 2) * 64;
    const int wn = (warp & 3) * 64;
#pragma unroll
    for (int mi = 0; mi < 4; mi++) {
#pragma unroll
        for (int ni = 0; ni < 8; ni++) {
            int gr = m0 + wm + mi * 16 + lm;
            int gc = n0 + wn + ni * 8 + lk * 2;
            float* p0 = Cm + (size_t)gr * N + gc;
            float* p1 = Cm + (size_t)(gr + 8) * N + gc;
            *(float2*)p0 = make_float2(acc[mi][ni][0], acc[mi][ni][1]);
            *(float2*)p1 = make_float2(acc[mi][ni][2], acc[mi][ni][3]);
        }
    }
}

// ---------------- RoPE + split/transpose ----------------------------------------
__global__ __launch_bounds__(128) void rope_split_kernel(
    const float* __restrict__ qkv, const float* __restrict__ cosg,
    const float* __restrict__ sing,
    float* __restrict__ Q, float* __restrict__ K, float* __restrict__ V)
{
    const int h = blockIdx.x;
    const int t = blockIdx.y;
    const int b = blockIdx.z;
    const int d = threadIdx.x;

    const float* base = qkv + ((size_t)(b * T_ + t)) * (3 * C_) + h * D_;
    const size_t outBase = ((size_t)((b * H_ + h) * T_ + t)) * D_;

    V[outBase + d] = base[2 * C_ + d];

    if (d < D_ / 2) {
        const float c = cosg[t * (D_ / 2) + d];
        const float s = sing[t * (D_ / 2) + d];
        float q1 = base[d];
        float q2 = base[d + D_ / 2];
        Q[outBase + d]          = q1 * c - q2 * s;
        Q[outBase + d + D_ / 2] = q1 * s + q2 * c;
        float k1 = base[C_ + d];
        float k2 = base[C_ + d + D_ / 2];
        K[outBase + d]          = k1 * c - k2 * s;
        K[outBase + d + D_ / 2] = k1 * s + k2 * c;
    }
}

// ---------------- tf32 MMA flash attention (unchanged from R2) ------------------
#define QS_FLOATS (64 * 132)
#define KS_FLOATS (64 * 68)
#define VS_FLOATS (64 * 68)
#define PS_FLOATS (16 * 132)
#define ATTN_SMEM_FLOATS (QS_FLOATS + KS_FLOATS + VS_FLOATS + PS_FLOATS)

__global__ __launch_bounds__(128, 2) void attn_mma_kernel(
    const float* __restrict__ Q, const float* __restrict__ K,
    const float* __restrict__ V)
{
    extern __shared__ float sm[];
    float* Qs = sm;
    float* Ks = Qs + QS_FLOATS;
    float* Vs = Ks + KS_FLOATS;
    float* Ps = Vs + VS_FLOATS;

    const int qb = blockIdx.x;
    const int bh = blockIdx.y;
    const int b = bh >> 4;
    const int h = bh & 15;
    const int tid = threadIdx.x;
    const int w = tid >> 5;
    const int lane = tid & 31;
    const int lm = lane >> 2;
    const int lk = lane & 3;
    const int q0 = qb * 64;

    const float* Qg = Q + ((size_t)bh * T_ + q0) * D_;
    const float* Kg = K + (size_t)bh * T_ * D_;
    const float* Vg = V + (size_t)bh * T_ * D_;

#pragma unroll
    for (int it = 0; it < 16; it++) {
        int idx = tid + it * 128;
        int r = idx >> 5;
        int c4 = (idx & 31) * 4;
        float4 q4 = *(const float4*)(Qg + (size_t)r * D_ + c4);
        int kt = c4 >> 3;
        int rh = ((c4 & 7) >= 4) ? 2 : 0;
        int rb = ((r & 15) >= 8) ? 1 : 0;
        float* tp = &Qs[((r >> 4) * 16 + kt) * 132 + rh + rb];
        int lf = (r & 7) << 2;
        tp[(lf + 0) * 4] = to_tf32(q4.x);
        tp[(lf + 1) * 4] = to_tf32(q4.y);
        tp[(lf + 2) * 4] = to_tf32(q4.z);
        tp[(lf + 3) * 4] = to_tf32(q4.w);
    }

    float m0 = -1e30f, m1 = -1e30f, l0 = 0.0f, l1 = 0.0f;
    float oacc[16][4];
#pragma unroll
    for (int ni = 0; ni < 16; ni++)
#pragma unroll
        for (int r = 0; r < 4; r++) oacc[ni][r] = 0.0f;

    const float scale = 0.08838834764831845f;
    const int nkv = (q0 + 64) / 32;
    const int row0g = q0 + w * 16 + lm;
    const int row1g = row0g + 8;

    for (int kt = 0; kt < nkv; kt++) {
        const int kv0 = kt * 32;
        __syncthreads();
#pragma unroll
        for (int it = 0; it < 8; it++) {
            int idx = tid + it * 128;
            int r = idx >> 5;
            int c4 = (idx & 31) * 4;
            size_t goff = (size_t)(kv0 + r) * D_ + c4;
            float4 k4 = *(const float4*)(Kg + goff);
            float4 v4 = *(const float4*)(Vg + goff);
            int dkt = c4 >> 3;
            int rhK = ((c4 & 7) >= 4) ? 1 : 0;
            {
                float* tp = &Ks[((r >> 3) * 16 + dkt) * 68 + rhK];
                int lf = (r & 7) << 2;
                tp[(lf + 0) * 2] = to_tf32(k4.x);
                tp[(lf + 1) * 2] = to_tf32(k4.y);
                tp[(lf + 2) * 2] = to_tf32(k4.z);
                tp[(lf + 3) * 2] = to_tf32(k4.w);
            }
            {
                int rhV = ((r & 7) >= 4) ? 1 : 0;
                float* tp = &Vs[((r >> 3) * 16 + dkt) * 68 + rhV];
                int dbase = c4 & 7;
                int kl = r & 3;
                tp[((dbase + 0) * 4 + kl) * 2] = to_tf32(v4.x);
                tp[((dbase + 1) * 4 + kl) * 2] = to_tf32(v4.y);
                tp[((dbase + 2) * 4 + kl) * 2] = to_tf32(v4.z);
                tp[((dbase + 3) * 4 + kl) * 2] = to_tf32(v4.w);
            }
        }
        __syncthreads();

        float sacc[4][4];
#pragma unroll
        for (int ni = 0; ni < 4; ni++)
#pragma unroll
            for (int r = 0; r < 4; r++) sacc[ni][r] = 0.0f;

#pragma unroll
        for (int dk = 0; dk < 16; dk++) {
            float afr[4];
            *(float4*)afr = *(float4*)&Qs[(w * 16 + dk) * 132 + lane * 4];
#pragma unroll
            for (int ni = 0; ni < 4; ni++) {
                float bfr[2];
                *(float2*)bfr = *(float2*)&Ks[(ni * 16 + dk) * 68 + lane * 2];
                mma_tf32(sacc[ni], afr, bfr);
            }
        }

        const bool needMask = (kt >= 2 * qb);
#pragma unroll
        for (int ni = 0; ni < 4; ni++) {
            int c0 = kv0 + ni * 8 + 2 * lk;
#pragma unroll
            for (int r = 0; r < 4; r++) sacc[ni][r] *= scale;
            if (needMask) {
                if (c0     > row0g) sacc[ni][0] = -1e30f;
                if (c0 + 1 > row0g) sacc[ni][1] = -1e30f;
                if (c0     > row1g) sacc[ni][2] = -1e30f;
                if (c0 + 1 > row1g) sacc[ni][3] = -1e30f;
            }
        }

        float rmax0 = -1e30f, rmax1 = -1e30f;
#pragma unroll
        for (int ni = 0; ni < 4; ni++) {
            rmax0 = fmaxf(rmax0, fmaxf(sacc[ni][0], sacc[ni][1]));
            rmax1 = fmaxf(rmax1, fmaxf(sacc[ni][2], sacc[ni][3]));
        }
        rmax0 = fmaxf(rmax0, __shfl_xor_sync(0xffffffffu, rmax0, 1));
        rmax0 = fmaxf(rmax0, __shfl_xor_sync(0xffffffffu, rmax0, 2));
        rmax1 = fmaxf(rmax1, __shfl_xor_sync(0xffffffffu, rmax1, 1));
        rmax1 = fmaxf(rmax1, __shfl_xor_sync(0xffffffffu, rmax1, 2));
        float mn0 = fmaxf(m0, rmax0);
        float mn1 = fmaxf(m1, rmax1);
        float al0 = __expf(m0 - mn0);
        float al1 = __expf(m1 - mn1);
        float rs0 = 0.0f, rs1 = 0.0f;
#pragma unroll
        for (int ni = 0; ni < 4; ni++) {
            sacc[ni][0] = __expf(sacc[ni][0] - mn0);
            sacc[ni][1] = __expf(sacc[ni][1] - mn0);
            sacc[ni][2] = __expf(sacc[ni][2] - mn1);
            sacc[ni][3] = __expf(sacc[ni][3] - mn1);
            rs0 += sacc[ni][0] + sacc[ni][1];
            rs1 += sacc[ni][2] + sacc[ni][3];
        }
        rs0 += __shfl_xor_sync(0xffffffffu, rs0, 1);
        rs0 += __shfl_xor_sync(0xffffffffu, rs0, 2);
        rs1 += __shfl_xor_sync(0xffffffffu, rs1, 1);
        rs1 += __shfl_xor_sync(0xffffffffu, rs1, 2);
        l0 = l0 * al0 + rs0;
        l1 = l1 * al1 + rs1;
        m0 = mn0;
        m1 = mn1;
#pragma unroll
        for (int ni = 0; ni < 16; ni++) {
            oacc[ni][0] *= al0; oacc[ni][1] *= al0;
            oacc[ni][2] *= al1; oacc[ni][3] *= al1;
        }

#pragma unroll
        for (int ni = 0; ni < 4; ni++) {
            float* tp = &Ps[(w * 4 + ni) * 132];
            int c0 = 2 * lk;
            int lf0 = (lm << 2) | (c0 & 3);
            int rh0 = (c0 >= 4) ? 2 : 0;
            tp[lf0 * 4 + rh0]     = to_tf32(sacc[ni][0]);
            tp[lf0 * 4 + rh0 + 1] = to_tf32(sacc[ni][2]);
            int c1 = 2 * lk + 1;
            int lf1 = (lm << 2) | (c1 & 3);
            int rh1 = (c1 >= 4) ? 2 : 0;
            tp[lf1 * 4 + rh1]     = to_tf32(sacc[ni][1]);
            tp[lf1 * 4 + rh1 + 1] = to_tf32(sacc[ni][3]);
        }
        __syncwarp();

#pragma unroll
        for (int kt2 = 0; kt2 < 4; kt2++) {
            float afr[4];
            *(float4*)afr = *(float4*)&Ps[(w * 4 + kt2) * 132 + lane * 4];
#pragma unroll
            for (int ni = 0; ni < 16; ni++) {
                float bfr[2];
                *(float2*)bfr = *(float2*)&Vs[(kt2 * 16 + ni) * 68 + lane * 2];
                mma_tf32(oacc[ni], afr, bfr);
            }
        }
    }

    float inv0 = 1.0f / l0;
    float inv1 = 1.0f / l1;
    float* out0 = g_attn + ((size_t)(b * T_ + row0g)) * C_ + h * D_;
    float* out1 = g_attn + ((size_t)(b * T_ + row1g)) * C_ + h * D_;
#pragma unroll
    for (int ni = 0; ni < 16; ni++) {
        int col = ni * 8 + 2 * lk;
        *(float2*)(out0 + col) = make_float2(oacc[ni][0] * inv0, oacc[ni][1] * inv0);
        *(float2*)(out1 + col) = make_float2(oacc[ni][2] * inv1, oacc[ni][3] * inv1);
    }
}

// ---------------- launch -------------------------------------------------------
extern "C" void kernel_launch(void* const* d_in, const int* in_sizes, int n_in,
                              void* d_out, int out_size)
{
    const float* x      = (const float*)d_in[0];
    const float* cosg   = (const float*)d_in[1];
    const float* sing   = (const float*)d_in[2];
    const float* W_qkv  = (const float*)d_in[3];
    const float* W_proj = (const float*)d_in[4];
    float* out = (float*)d_out;

    float* qkv;  cudaGetSymbolAddress((void**)&qkv,  g_qkv);
    float* Qb;   cudaGetSymbolAddress((void**)&Qb,   g_Q);
    float* Kb;   cudaGetSymbolAddress((void**)&Kb,   g_K);
    float* Vb;   cudaGetSymbolAddress((void**)&Vb,   g_V);
    float* attn; cudaGetSymbolAddress((void**)&attn, g_attn);

    const int M = B_ * T_;
    const size_t gemmSmem = GEMM_SMEM_FLOATS * sizeof(float);

    cudaFuncSetAttribute(mma_gemm2_kernel,
                         cudaFuncAttributeMaxDynamicSharedMemorySize, (int)gemmSmem);
    cudaFuncSetAttribute(attn_mma_kernel,
                         cudaFuncAttributeMaxDynamicSharedMemorySize,
                         ATTN_SMEM_FLOATS * sizeof(float));

    // 1) qkv = x @ W_qkv
    {
        dim3 grid(3 * C_ / GBN, M / GBM);
        mma_gemm2_kernel<<<grid, 256, gemmSmem>>>(x, W_qkv, qkv, M, 3 * C_, C_);
    }
    // 2) RoPE + split
    {
        dim3 grid(H_, T_, B_);
        rope_split_kernel<<<grid, 128>>>(qkv, cosg, sing, Qb, Kb, Vb);
    }
    // 3) attention
    {
        dim3 grid(T_ / 64, B_ * H_);
        attn_mma_kernel<<<grid, 128, ATTN_SMEM_FLOATS * sizeof(float)>>>(Qb, Kb, Vb);
    }
    // 4) out = attn @ W_proj
    {
        dim3 grid(C_ / GBN, M / GBM);
        mma_gemm2_kernel<<<grid, 256, gemmSmem>>>(attn, W_proj, out, M, C_, C_);
    }
}

// round 7
// speedup vs baseline: 4.1791x; 1.1787x over previous
#include <cuda_runtime.h>
#include <cstdio>
#include <cstdint>

#define B_ 2
#define T_ 2048
#define C_ 2048
#define H_ 16
#define D_ 128

// ---------------- scratch (device globals: no runtime allocation) ----------------
__device__ float g_qkv[(size_t)B_ * T_ * 3 * C_];
__device__ float g_Q[(size_t)B_ * H_ * T_ * D_];
__device__ float g_K[(size_t)B_ * H_ * T_ * D_];
__device__ float g_V[(size_t)B_ * H_ * T_ * D_];
__device__ float g_attn[(size_t)B_ * T_ * C_];
__device__ float g_xc[(size_t)B_ * T_ * C_];          // tf32-rounded x
__device__ float g_wqkvC[(size_t)C_ * 3 * C_];        // tf32-rounded W_qkv
__device__ float g_wprojC[(size_t)C_ * C_];           // tf32-rounded W_proj

// ---------------- helpers -------------------------------------------------------
__device__ __forceinline__ float to_tf32(float x) {
    unsigned u;
    asm("cvt.rna.tf32.f32 %0, %1;" : "=r"(u) : "f"(x));
    return __uint_as_float(u);
}

__device__ __forceinline__ void mma_tf32(float c[4], const float a[4], const float b[2]) {
    asm volatile(
        "mma.sync.aligned.m16n8k8.row.col.f32.tf32.tf32.f32 "
        "{%0,%1,%2,%3}, {%4,%5,%6,%7}, {%8,%9}, {%0,%1,%2,%3};"
        : "+f"(c[0]), "+f"(c[1]), "+f"(c[2]), "+f"(c[3])
        : "r"(__float_as_uint(a[0])), "r"(__float_as_uint(a[1])),
          "r"(__float_as_uint(a[2])), "r"(__float_as_uint(a[3])),
          "r"(__float_as_uint(b[0])), "r"(__float_as_uint(b[1])));
}

__device__ __forceinline__ uint32_t smem_u32(const void* p) {
    uint32_t a;
    asm("{ .reg .u64 t; cvta.to.shared.u64 t, %1; cvt.u32.u64 %0, t; }" : "=r"(a) : "l"(p));
    return a;
}

#define CP_ASYNC16(dst, src) \
    asm volatile("cp.async.cg.shared.global [%0], [%1], 16;" :: "r"(dst), "l"(src) : "memory")
#define CP_COMMIT() asm volatile("cp.async.commit_group;" ::: "memory")

// ================= GEMM v3: cp.async 4-stage, 128x128 tile, warp 64x32 ==========
// A smem: [128 rows][20 floats]  (k-stride 20 -> conflict-free scalar frag loads)
// B smem: [16 k-rows][136 floats] (n-stride 136 -> conflict-free)
#define V3_BM 128
#define V3_BN 128
#define V3_BK 16
#define V3_APAD 20
#define V3_BPAD 136
#define V3_AFLOATS (V3_BM * V3_APAD)          // 2560
#define V3_BFLOATS (V3_BK * V3_BPAD)          // 2176
#define V3_STAGEF (V3_AFLOATS + V3_BFLOATS)   // 4736 floats = 18944 B
#define V3_NST 4
#define V3_SMEM_BYTES (V3_NST * V3_STAGEF * 4)  // 75776

__global__ __launch_bounds__(256, 2) void gemm_v3_kernel(
    const float* __restrict__ A, const float* __restrict__ W, float* __restrict__ Cm,
    int M, int N, int K)
{
    extern __shared__ float sm[];

    const int tid = threadIdx.x;
    const int warp = tid >> 5;
    const int lane = tid & 31;
    const int lm = lane >> 2;
    const int lk = lane & 3;

    const int m0 = blockIdx.y * V3_BM;
    const int n0 = blockIdx.x * V3_BN;
    const int wm = (warp >> 2) * 64;
    const int wn = (warp & 3) * 32;

    const uint32_t smb = smem_u32(sm);

    float acc[4][4][4];
#pragma unroll
    for (int mi = 0; mi < 4; mi++)
#pragma unroll
        for (int ni = 0; ni < 4; ni++)
#pragma unroll
            for (int r = 0; r < 4; r++) acc[mi][ni][r] = 0.0f;

    auto load_stage = [&](int s) {
        const int k0 = s * V3_BK;
        const uint32_t base = smb + (uint32_t)((s & (V3_NST - 1)) * V3_STAGEF * 4);
        // A: 512 chunks: id = tid + i*256; r=id>>2 (0..127), c=id&3 (k-quarter)
#pragma unroll
        for (int i = 0; i < 2; i++) {
            int id = tid + i * 256;
            int r = id >> 2, c = id & 3;
            uint32_t dst = base + (uint32_t)(r * (V3_APAD * 4) + c * 16);
            const float* src = A + (size_t)(m0 + r) * K + k0 + c * 4;
            CP_ASYNC16(dst, src);
        }
        // B: 512 chunks: k=id>>5 (0..15), n4=id&31
        const uint32_t bbase = base + V3_AFLOATS * 4;
#pragma unroll
        for (int i = 0; i < 2; i++) {
            int id = tid + i * 256;
            int k = id >> 5, n4 = id & 31;
            uint32_t dst = bbase + (uint32_t)(k * (V3_BPAD * 4) + n4 * 16);
            const float* src = W + (size_t)(k0 + k) * N + n0 + n4 * 4;
            CP_ASYNC16(dst, src);
        }
        CP_COMMIT();
    };

    const int nst = K / V3_BK;   // 128
    load_stage(0);
    load_stage(1);
    load_stage(2);

    for (int ks = 0; ks < nst; ks++) {
        asm volatile("cp.async.wait_group %0;" :: "n"(2) : "memory");
        __syncthreads();

        const float* As = sm + (size_t)(ks & (V3_NST - 1)) * V3_STAGEF;
        const float* Bs = As + V3_AFLOATS;

#pragma unroll
        for (int kk = 0; kk < V3_BK; kk += 8) {
            float afr[4][4];
#pragma unroll
            for (int mi = 0; mi < 4; mi++) {
                int row = wm + mi * 16 + lm;
                afr[mi][0] = As[row * V3_APAD + kk + lk];
                afr[mi][1] = As[(row + 8) * V3_APAD + kk + lk];
                afr[mi][2] = As[row * V3_APAD + kk + lk + 4];
                afr[mi][3] = As[(row + 8) * V3_APAD + kk + lk + 4];
            }
            float bfr[4][2];
#pragma unroll
            for (int ni = 0; ni < 4; ni++) {
                int col = wn + ni * 8 + lm;
                bfr[ni][0] = Bs[(kk + lk) * V3_BPAD + col];
                bfr[ni][1] = Bs[(kk + lk + 4) * V3_BPAD + col];
            }
#pragma unroll
            for (int mi = 0; mi < 4; mi++)
#pragma unroll
                for (int ni = 0; ni < 4; ni++)
                    mma_tf32(acc[mi][ni], afr[mi], bfr[ni]);
        }

        // Tail fix: ALWAYS commit a group each iteration so wait_group(2)
        // retires exactly the group for the stage consumed 3 iters later.
        // Without the empty commit, the last two stages are read un-awaited
        // (the post-timing divergence seen in R6).
        if (ks + 3 < nst) load_stage(ks + 3);
        else CP_COMMIT();
    }

    // epilogue
#pragma unroll
    for (int mi = 0; mi < 4; mi++) {
#pragma unroll
        for (int ni = 0; ni < 4; ni++) {
            int gr = m0 + wm + mi * 16 + lm;
            int gc = n0 + wn + ni * 8 + lk * 2;
            float* p0 = Cm + (size_t)gr * N + gc;
            float* p1 = Cm + (size_t)(gr + 8) * N + gc;
            *(float2*)p0 = make_float2(acc[mi][ni][0], acc[mi][ni][1]);
            *(float2*)p1 = make_float2(acc[mi][ni][2], acc[mi][ni][3]);
        }
    }
}

// ---------------- pre-pass: tf32 rounding ---------------------------------------
__global__ __launch_bounds__(256) void convert_tf32_kernel(
    const float* __restrict__ src, float* __restrict__ dst, int n4)
{
    int i = blockIdx.x * blockDim.x + threadIdx.x;
    if (i < n4) {
        float4 v = *(const float4*)(src + (size_t)i * 4);
        v.x = to_tf32(v.x); v.y = to_tf32(v.y);
        v.z = to_tf32(v.z); v.w = to_tf32(v.w);
        *(float4*)(dst + (size_t)i * 4) = v;
    }
}

// ---------------- RoPE + split/transpose ----------------------------------------
__global__ __launch_bounds__(128) void rope_split_kernel(
    const float* __restrict__ qkv, const float* __restrict__ cosg,
    const float* __restrict__ sing,
    float* __restrict__ Q, float* __restrict__ K, float* __restrict__ V)
{
    const int h = blockIdx.x;
    const int t = blockIdx.y;
    const int b = blockIdx.z;
    const int d = threadIdx.x;

    const float* base = qkv + ((size_t)(b * T_ + t)) * (3 * C_) + h * D_;
    const size_t outBase = ((size_t)((b * H_ + h) * T_ + t)) * D_;

    V[outBase + d] = base[2 * C_ + d];

    if (d < D_ / 2) {
        const float c = cosg[t * (D_ / 2) + d];
        const float s = sing[t * (D_ / 2) + d];
        float q1 = base[d];
        float q2 = base[d + D_ / 2];
        Q[outBase + d]          = q1 * c - q2 * s;
        Q[outBase + d + D_ / 2] = q1 * s + q2 * c;
        float k1 = base[C_ + d];
        float k2 = base[C_ + d + D_ / 2];
        K[outBase + d]          = k1 * c - k2 * s;
        K[outBase + d + D_ / 2] = k1 * s + k2 * c;
    }
}

// ---------------- tf32 MMA flash attention --------------------------------------
#define QS_FLOATS (64 * 132)
#define KS_FLOATS (64 * 68)
#define VS_FLOATS (64 * 68)
#define PS_FLOATS (16 * 132)
#define ATTN_SMEM_FLOATS (QS_FLOATS + KS_FLOATS + VS_FLOATS + PS_FLOATS)

__global__ __launch_bounds__(128, 2) void attn_mma_kernel(
    const float* __restrict__ Q, const float* __restrict__ K,
    const float* __restrict__ V)
{
    extern __shared__ float sm[];
    float* Qs = sm;
    float* Ks = Qs + QS_FLOATS;
    float* Vs = Ks + KS_FLOATS;
    float* Ps = Vs + VS_FLOATS;

    const int qb = blockIdx.x;
    const int bh = blockIdx.y;
    const int b = bh >> 4;
    const int h = bh & 15;
    const int tid = threadIdx.x;
    const int w = tid >> 5;
    const int lane = tid & 31;
    const int lm = lane >> 2;
    const int lk = lane & 3;
    const int q0 = qb * 64;

    const float* Qg = Q + ((size_t)bh * T_ + q0) * D_;
    const float* Kg = K + (size_t)bh * T_ * D_;
    const float* Vg = V + (size_t)bh * T_ * D_;

#pragma unroll
    for (int it = 0; it < 16; it++) {
        int idx = tid + it * 128;
        int r = idx >> 5;
        int c4 = (idx & 31) * 4;
        float4 q4 = *(const float4*)(Qg + (size_t)r * D_ + c4);
        int kt = c4 >> 3;
        int rh = ((c4 & 7) >= 4) ? 2 : 0;
        int rb = ((r & 15) >= 8) ? 1 : 0;
        float* tp = &Qs[((r >> 4) * 16 + kt) * 132 + rh + rb];
        int lf = (r & 7) << 2;
        tp[(lf + 0) * 4] = to_tf32(q4.x);
        tp[(lf + 1) * 4] = to_tf32(q4.y);
        tp[(lf + 2) * 4] = to_tf32(q4.z);
        tp[(lf + 3) * 4] = to_tf32(q4.w);
    }

    float m0 = -1e30f, m1 = -1e30f, l0 = 0.0f, l1 = 0.0f;
    float oacc[16][4];
#pragma unroll
    for (int ni = 0; ni < 16; ni++)
#pragma unroll
        for (int r = 0; r < 4; r++) oacc[ni][r] = 0.0f;

    const float scale = 0.08838834764831845f;
    const int nkv = (q0 + 64) / 32;
    const int row0g = q0 + w * 16 + lm;
    const int row1g = row0g + 8;

    for (int kt = 0; kt < nkv; kt++) {
        const int kv0 = kt * 32;
        __syncthreads();
#pragma unroll
        for (int it = 0; it < 8; it++) {
            int idx = tid + it * 128;
            int r = idx >> 5;
            int c4 = (idx & 31) * 4;
            size_t goff = (size_t)(kv0 + r) * D_ + c4;
            float4 k4 = *(const float4*)(Kg + goff);
            float4 v4 = *(const float4*)(Vg + goff);
            int dkt = c4 >> 3;
            int rhK = ((c4 & 7) >= 4) ? 1 : 0;
            {
                float* tp = &Ks[((r >> 3) * 16 + dkt) * 68 + rhK];
                int lf = (r & 7) << 2;
                tp[(lf + 0) * 2] = to_tf32(k4.x);
                tp[(lf + 1) * 2] = to_tf32(k4.y);
                tp[(lf + 2) * 2] = to_tf32(k4.z);
                tp[(lf + 3) * 2] = to_tf32(k4.w);
            }
            {
                int rhV = ((r & 7) >= 4) ? 1 : 0;
                float* tp = &Vs[((r >> 3) * 16 + dkt) * 68 + rhV];
                int dbase = c4 & 7;
                int kl = r & 3;
                tp[((dbase + 0) * 4 + kl) * 2] = to_tf32(v4.x);
                tp[((dbase + 1) * 4 + kl) * 2] = to_tf32(v4.y);
                tp[((dbase + 2) * 4 + kl) * 2] = to_tf32(v4.z);
                tp[((dbase + 3) * 4 + kl) * 2] = to_tf32(v4.w);
            }
        }
        __syncthreads();

        float sacc[4][4];
#pragma unroll
        for (int ni = 0; ni < 4; ni++)
#pragma unroll
            for (int r = 0; r < 4; r++) sacc[ni][r] = 0.0f;

#pragma unroll
        for (int dk = 0; dk < 16; dk++) {
            float afr[4];
            *(float4*)afr = *(float4*)&Qs[(w * 16 + dk) * 132 + lane * 4];
#pragma unroll
            for (int ni = 0; ni < 4; ni++) {
                float bfr[2];
                *(float2*)bfr = *(float2*)&Ks[(ni * 16 + dk) * 68 + lane * 2];
                mma_tf32(sacc[ni], afr, bfr);
            }
        }

        const bool needMask = (kt >= 2 * qb);
#pragma unroll
        for (int ni = 0; ni < 4; ni++) {
            int c0 = kv0 + ni * 8 + 2 * lk;
#pragma unroll
            for (int r = 0; r < 4; r++) sacc[ni][r] *= scale;
            if (needMask) {
                if (c0     > row0g) sacc[ni][0] = -1e30f;
                if (c0 + 1 > row0g) sacc[ni][1] = -1e30f;
                if (c0     > row1g) sacc[ni][2] = -1e30f;
                if (c0 + 1 > row1g) sacc[ni][3] = -1e30f;
            }
        }

        float rmax0 = -1e30f, rmax1 = -1e30f;
#pragma unroll
        for (int ni = 0; ni < 4; ni++) {
            rmax0 = fmaxf(rmax0, fmaxf(sacc[ni][0], sacc[ni][1]));
            rmax1 = fmaxf(rmax1, fmaxf(sacc[ni][2], sacc[ni][3]));
        }
        rmax0 = fmaxf(rmax0, __shfl_xor_sync(0xffffffffu, rmax0, 1));
        rmax0 = fmaxf(rmax0, __shfl_xor_sync(0xffffffffu, rmax0, 2));
        rmax1 = fmaxf(rmax1, __shfl_xor_sync(0xffffffffu, rmax1, 1));
        rmax1 = fmaxf(rmax1, __shfl_xor_sync(0xffffffffu, rmax1, 2));
        float mn0 = fmaxf(m0, rmax0);
        float mn1 = fmaxf(m1, rmax1);
        float al0 = __expf(m0 - mn0);
        float al1 = __expf(m1 - mn1);
        float rs0 = 0.0f, rs1 = 0.0f;
#pragma unroll
        for (int ni = 0; ni < 4; ni++) {
            sacc[ni][0] = __expf(sacc[ni][0] - mn0);
            sacc[ni][1] = __expf(sacc[ni][1] - mn0);
            sacc[ni][2] = __expf(sacc[ni][2] - mn1);
            sacc[ni][3] = __expf(sacc[ni][3] - mn1);
            rs0 += sacc[ni][0] + sacc[ni][1];
            rs1 += sacc[ni][2] + sacc[ni][3];
        }
        rs0 += __shfl_xor_sync(0xffffffffu, rs0, 1);
        rs0 += __shfl_xor_sync(0xffffffffu, rs0, 2);
        rs1 += __shfl_xor_sync(0xffffffffu, rs1, 1);
        rs1 += __shfl_xor_sync(0xffffffffu, rs1, 2);
        l0 = l0 * al0 + rs0;
        l1 = l1 * al1 + rs1;
        m0 = mn0;
        m1 = mn1;
#pragma unroll
        for (int ni = 0; ni < 16; ni++) {
            oacc[ni][0] *= al0; oacc[ni][1] *= al0;
            oacc[ni][2] *= al1; oacc[ni][3] *= al1;
        }

#pragma unroll
        for (int ni = 0; ni < 4; ni++) {
            float* tp = &Ps[(w * 4 + ni) * 132];
            int c0 = 2 * lk;
            int lf0 = (lm << 2) | (c0 & 3);
            int rh0 = (c0 >= 4) ? 2 : 0;
            tp[lf0 * 4 + rh0]     = to_tf32(sacc[ni][0]);
            tp[lf0 * 4 + rh0 + 1] = to_tf32(sacc[ni][2]);
            int c1 = 2 * lk + 1;
            int lf1 = (lm << 2) | (c1 & 3);
            int rh1 = (c1 >= 4) ? 2 : 0;
            tp[lf1 * 4 + rh1]     = to_tf32(sacc[ni][1]);
            tp[lf1 * 4 + rh1 + 1] = to_tf32(sacc[ni][3]);
        }
        __syncwarp();

#pragma unroll
        for (int kt2 = 0; kt2 < 4; kt2++) {
            float afr[4];
            *(float4*)afr = *(float4*)&Ps[(w * 4 + kt2) * 132 + lane * 4];
#pragma unroll
            for (int ni = 0; ni < 16; ni++) {
                float bfr[2];
                *(float2*)bfr = *(float2*)&Vs[(kt2 * 16 + ni) * 68 + lane * 2];
                mma_tf32(oacc[ni], afr, bfr);
            }
        }
    }

    float inv0 = 1.0f / l0;
    float inv1 = 1.0f / l1;
    float* out0 = g_attn + ((size_t)(b * T_ + row0g)) * C_ + h * D_;
    float* out1 = g_attn + ((size_t)(b * T_ + row1g)) * C_ + h * D_;
#pragma unroll
    for (int ni = 0; ni < 16; ni++) {
        int col = ni * 8 + 2 * lk;
        *(float2*)(out0 + col) = make_float2(to_tf32(oacc[ni][0] * inv0),
                                             to_tf32(oacc[ni][1] * inv0));
        *(float2*)(out1 + col) = make_float2(to_tf32(oacc[ni][2] * inv1),
                                             to_tf32(oacc[ni][3] * inv1));
    }
}

// ---------------- launch -------------------------------------------------------
extern "C" void kernel_launch(void* const* d_in, const int* in_sizes, int n_in,
                              void* d_out, int out_size)
{
    const float* x      = (const float*)d_in[0];
    const float* cosg   = (const float*)d_in[1];
    const float* sing   = (const float*)d_in[2];
    const float* W_qkv  = (const float*)d_in[3];
    const float* W_proj = (const float*)d_in[4];
    float* out = (float*)d_out;

    float* qkv;    cudaGetSymbolAddress((void**)&qkv,    g_qkv);
    float* Qb;     cudaGetSymbolAddress((void**)&Qb,     g_Q);
    float* Kb;     cudaGetSymbolAddress((void**)&Kb,     g_K);
    float* Vb;     cudaGetSymbolAddress((void**)&Vb,     g_V);
    float* attn;   cudaGetSymbolAddress((void**)&attn,   g_attn);
    float* xc;     cudaGetSymbolAddress((void**)&xc,     g_xc);
    float* wqkvC;  cudaGetSymbolAddress((void**)&wqkvC,  g_wqkvC);
    float* wprojC; cudaGetSymbolAddress((void**)&wprojC, g_wprojC);

    const int M = B_ * T_;   // 4096

    cudaFuncSetAttribute(gemm_v3_kernel,
                         cudaFuncAttributeMaxDynamicSharedMemorySize, V3_SMEM_BYTES);
    cudaFuncSetAttribute(attn_mma_kernel,
                         cudaFuncAttributeMaxDynamicSharedMemorySize,
                         ATTN_SMEM_FLOATS * sizeof(float));

    // 0) tf32-round x / W_qkv / W_proj in gmem (so cp.async data is pre-rounded)
    {
        int n4x = (M * C_) / 4;
        convert_tf32_kernel<<<(n4x + 255) / 256, 256>>>(x, xc, n4x);
        int n4q = (C_ * 3 * C_) / 4;
        convert_tf32_kernel<<<(n4q + 255) / 256, 256>>>(W_qkv, wqkvC, n4q);
        int n4p = (C_ * C_) / 4;
        convert_tf32_kernel<<<(n4p + 255) / 256, 256>>>(W_proj, wprojC, n4p);
    }

    // 1) qkv = xc @ wqkvC
    {
        dim3 grid(3 * C_ / V3_BN, M / V3_BM);   // (48, 32)
        gemm_v3_kernel<<<grid, 256, V3_SMEM_BYTES>>>(xc, wqkvC, qkv, M, 3 * C_, C_);
    }
    // 2) RoPE + split
    {
        dim3 grid(H_, T_, B_);
        rope_split_kernel<<<grid, 128>>>(qkv, cosg, sing, Qb, Kb, Vb);
    }
    // 3) attention -> g_attn (tf32-rounded)
    {
        dim3 grid(T_ / 64, B_ * H_);
        attn_mma_kernel<<<grid, 128, ATTN_SMEM_FLOATS * sizeof(float)>>>(Qb, Kb, Vb);
    }
    // 4) out = attn @ wprojC
    {
        dim3 grid(C_ / V3_BN, M / V3_BM);       // (16, 32)
        gemm_v3_kernel<<<grid, 256, V3_SMEM_BYTES>>>(attn, wprojC, out, M, C_, C_);
    }
}

// round 8
// speedup vs baseline: 4.4450x; 1.0636x over previous
#include <cuda_runtime.h>
#include <cstdio>
#include <cstdint>

#define B_ 2
#define T_ 2048
#define C_ 2048
#define H_ 16
#define D_ 128

// ---------------- scratch (device globals: no runtime allocation) ----------------
__device__ float g_qkv[(size_t)B_ * T_ * 3 * C_];
__device__ float g_Q[(size_t)B_ * H_ * T_ * D_];
__device__ float g_K[(size_t)B_ * H_ * T_ * D_];
__device__ float g_V[(size_t)B_ * H_ * T_ * D_];
__device__ float g_attn[(size_t)B_ * T_ * C_];
__device__ float g_xc[(size_t)B_ * T_ * C_];          // tf32-rounded x
__device__ float g_wqkvC[(size_t)C_ * 3 * C_];        // tf32-rounded W_qkv
__device__ float g_wprojC[(size_t)C_ * C_];           // tf32-rounded W_proj

// ---------------- helpers -------------------------------------------------------
__device__ __forceinline__ float to_tf32(float x) {
    unsigned u;
    asm("cvt.rna.tf32.f32 %0, %1;" : "=r"(u) : "f"(x));
    return __uint_as_float(u);
}

__device__ __forceinline__ void mma_tf32(float c[4], const float a[4], const float b[2]) {
    asm volatile(
        "mma.sync.aligned.m16n8k8.row.col.f32.tf32.tf32.f32 "
        "{%0,%1,%2,%3}, {%4,%5,%6,%7}, {%8,%9}, {%0,%1,%2,%3};"
        : "+f"(c[0]), "+f"(c[1]), "+f"(c[2]), "+f"(c[3])
        : "r"(__float_as_uint(a[0])), "r"(__float_as_uint(a[1])),
          "r"(__float_as_uint(a[2])), "r"(__float_as_uint(a[3])),
          "r"(__float_as_uint(b[0])), "r"(__float_as_uint(b[1])));
}

__device__ __forceinline__ uint32_t smem_u32(const void* p) {
    uint32_t a;
    asm("{ .reg .u64 t; cvta.to.shared.u64 t, %1; cvt.u32.u64 %0, t; }" : "=r"(a) : "l"(p));
    return a;
}

#define CP_ASYNC16(dst, src) \
    asm volatile("cp.async.cg.shared.global [%0], [%1], 16;" :: "r"(dst), "l"(src) : "memory")
#define CP_COMMIT() asm volatile("cp.async.commit_group;" ::: "memory")

// ================= GEMM v4: cp.async, BK=32, 3 stages, 128x128, warp 64x32 ======
// A smem: [128 rows][36 floats]  (bank = 4*row + k  -> conflict-free frag loads)
// B smem: [32 k-rows][136 floats] (bank = 8*k + col -> conflict-free)
#define V4_BM 128
#define V4_BN 128
#define V4_BK 32
#define V4_APAD 36
#define V4_BPAD 136
#define V4_AFLOATS (V4_BM * V4_APAD)          // 4608
#define V4_BFLOATS (V4_BK * V4_BPAD)          // 4352
#define V4_STAGEF (V4_AFLOATS + V4_BFLOATS)   // 8960 floats = 35840 B
#define V4_NST 3
#define V4_SMEM_BYTES (V4_NST * V4_STAGEF * 4)  // 107520

__global__ __launch_bounds__(256, 2) void gemm_v4_kernel(
    const float* __restrict__ A, const float* __restrict__ W, float* __restrict__ Cm,
    int M, int N, int K)
{
    extern __shared__ float sm[];

    const int tid = threadIdx.x;
    const int warp = tid >> 5;
    const int lane = tid & 31;
    const int lm = lane >> 2;
    const int lk = lane & 3;

    const int m0 = blockIdx.y * V4_BM;
    const int n0 = blockIdx.x * V4_BN;
    const int wm = (warp >> 2) * 64;
    const int wn = (warp & 3) * 32;

    const uint32_t smb = smem_u32(sm);

    float acc[4][4][4];
#pragma unroll
    for (int mi = 0; mi < 4; mi++)
#pragma unroll
        for (int ni = 0; ni < 4; ni++)
#pragma unroll
            for (int r = 0; r < 4; r++) acc[mi][ni][r] = 0.0f;

    auto load_stage = [&](int s) {
        const int k0 = s * V4_BK;
        const uint32_t base = smb + (uint32_t)((s % V4_NST) * V4_STAGEF * 4);
        // A: 1024 chunks of 16B: r = id>>3 (0..127), c = id&7 (k-eighth)
#pragma unroll
        for (int i = 0; i < 4; i++) {
            int id = tid + i * 256;
            int r = id >> 3, c = id & 7;
            uint32_t dst = base + (uint32_t)(r * (V4_APAD * 4) + c * 16);
            const float* src = A + (size_t)(m0 + r) * K + k0 + c * 4;
            CP_ASYNC16(dst, src);
        }
        // B: 1024 chunks: k = id>>5 (0..31), n4 = id&31
        const uint32_t bbase = base + V4_AFLOATS * 4;
#pragma unroll
        for (int i = 0; i < 4; i++) {
            int id = tid + i * 256;
            int k = id >> 5, n4 = id & 31;
            uint32_t dst = bbase + (uint32_t)(k * (V4_BPAD * 4) + n4 * 16);
            const float* src = W + (size_t)(k0 + k) * N + n0 + n4 * 4;
            CP_ASYNC16(dst, src);
        }
        CP_COMMIT();
    };

    const int nst = K / V4_BK;   // 64
    load_stage(0);
    load_stage(1);

    for (int ks = 0; ks < nst; ks++) {
        // retire group for slab ks (exactly one commit per iter keeps accounting exact)
        asm volatile("cp.async.wait_group %0;" :: "n"(1) : "memory");
        __syncthreads();

        const float* As = sm + (size_t)(ks % V4_NST) * V4_STAGEF;
        const float* Bs = As + V4_AFLOATS;

#pragma unroll
        for (int kk = 0; kk < V4_BK; kk += 8) {
            float afr[4][4];
#pragma unroll
            for (int mi = 0; mi < 4; mi++) {
                int row = wm + mi * 16 + lm;
                afr[mi][0] = As[row * V4_APAD + kk + lk];
                afr[mi][1] = As[(row + 8) * V4_APAD + kk + lk];
                afr[mi][2] = As[row * V4_APAD + kk + lk + 4];
                afr[mi][3] = As[(row + 8) * V4_APAD + kk + lk + 4];
            }
            float bfr[4][2];
#pragma unroll
            for (int ni = 0; ni < 4; ni++) {
                int col = wn + ni * 8 + lm;
                bfr[ni][0] = Bs[(kk + lk) * V4_BPAD + col];
                bfr[ni][1] = Bs[(kk + lk + 4) * V4_BPAD + col];
            }
#pragma unroll
            for (int mi = 0; mi < 4; mi++)
#pragma unroll
                for (int ni = 0; ni < 4; ni++)
                    mma_tf32(acc[mi][ni], afr[mi], bfr[ni]);
        }

        // prefetch slab ks+2 into slot (ks+2)%3 == (ks-1)%3 (sync-protected);
        // always commit so wait_group(1) retires exactly slab ks+1 next iter.
        if (ks + 2 < nst) load_stage(ks + 2);
        else CP_COMMIT();
    }

    // epilogue
#pragma unroll
    for (int mi = 0; mi < 4; mi++) {
#pragma unroll
        for (int ni = 0; ni < 4; ni++) {
            int gr = m0 + wm + mi * 16 + lm;
            int gc = n0 + wn + ni * 8 + lk * 2;
            float* p0 = Cm + (size_t)gr * N + gc;
            float* p1 = Cm + (size_t)(gr + 8) * N + gc;
            *(float2*)p0 = make_float2(acc[mi][ni][0], acc[mi][ni][1]);
            *(float2*)p1 = make_float2(acc[mi][ni][2], acc[mi][ni][3]);
        }
    }
}

// ---------------- pre-pass: tf32 rounding ---------------------------------------
__global__ __launch_bounds__(256) void convert_tf32_kernel(
    const float* __restrict__ src, float* __restrict__ dst, int n4)
{
    int i = blockIdx.x * blockDim.x + threadIdx.x;
    if (i < n4) {
        float4 v = *(const float4*)(src + (size_t)i * 4);
        v.x = to_tf32(v.x); v.y = to_tf32(v.y);
        v.z = to_tf32(v.z); v.w = to_tf32(v.w);
        *(float4*)(dst + (size_t)i * 4) = v;
    }
}

// ---------------- RoPE + split/transpose ----------------------------------------
__global__ __launch_bounds__(128) void rope_split_kernel(
    const float* __restrict__ qkv, const float* __restrict__ cosg,
    const float* __restrict__ sing,
    float* __restrict__ Q, float* __restrict__ K, float* __restrict__ V)
{
    const int h = blockIdx.x;
    const int t = blockIdx.y;
    const int b = blockIdx.z;
    const int d = threadIdx.x;

    const float* base = qkv + ((size_t)(b * T_ + t)) * (3 * C_) + h * D_;
    const size_t outBase = ((size_t)((b * H_ + h) * T_ + t)) * D_;

    V[outBase + d] = base[2 * C_ + d];

    if (d < D_ / 2) {
        const float c = cosg[t * (D_ / 2) + d];
        const float s = sing[t * (D_ / 2) + d];
        float q1 = base[d];
        float q2 = base[d + D_ / 2];
        Q[outBase + d]          = q1 * c - q2 * s;
        Q[outBase + d + D_ / 2] = q1 * s + q2 * c;
        float k1 = base[C_ + d];
        float k2 = base[C_ + d + D_ / 2];
        K[outBase + d]          = k1 * c - k2 * s;
        K[outBase + d + D_ / 2] = k1 * s + k2 * c;
    }
}

// ---------------- tf32 MMA flash attention, BQ=128 (8 warps) --------------------
#define AQ_BQ 128
#define QS_FLOATS (128 * 132)     // 8 rt x 16 kt tiles
#define KS_FLOATS (64 * 68)
#define VS_FLOATS (64 * 68)
#define PS_FLOATS (32 * 132)      // 8 warps x 4 tiles
#define ATTN_SMEM_FLOATS (QS_FLOATS + KS_FLOATS + VS_FLOATS + PS_FLOATS)

__global__ __launch_bounds__(256, 1) void attn_mma_kernel(
    const float* __restrict__ Q, const float* __restrict__ K,
    const float* __restrict__ V)
{
    extern __shared__ float sm[];
    float* Qs = sm;
    float* Ks = Qs + QS_FLOATS;
    float* Vs = Ks + KS_FLOATS;
    float* Ps = Vs + VS_FLOATS;

    const int qb = blockIdx.x;
    const int bh = blockIdx.y;
    const int b = bh >> 4;
    const int h = bh & 15;
    const int tid = threadIdx.x;
    const int w = tid >> 5;          // 0..7
    const int lane = tid & 31;
    const int lm = lane >> 2;
    const int lk = lane & 3;
    const int q0 = qb * AQ_BQ;

    const float* Qg = Q + ((size_t)bh * T_ + q0) * D_;
    const float* Kg = K + (size_t)bh * T_ * D_;
    const float* Vg = V + (size_t)bh * T_ * D_;

    // ---- load Q tile (128x128) into A-fragment layout ----
#pragma unroll
    for (int it = 0; it < 16; it++) {
        int idx = tid + it * 256;
        int r = idx >> 5;                 // 0..127
        int c4 = (idx & 31) * 4;
        float4 q4 = *(const float4*)(Qg + (size_t)r * D_ + c4);
        int kt = c4 >> 3;
        int rh = ((c4 & 7) >= 4) ? 2 : 0;
        int rb = ((r & 15) >= 8) ? 1 : 0;
        float* tp = &Qs[((r >> 4) * 16 + kt) * 132 + rh + rb];
        int lf = (r & 7) << 2;
        tp[(lf + 0) * 4] = to_tf32(q4.x);
        tp[(lf + 1) * 4] = to_tf32(q4.y);
        tp[(lf + 2) * 4] = to_tf32(q4.z);
        tp[(lf + 3) * 4] = to_tf32(q4.w);
    }

    float m0 = -1e30f, m1 = -1e30f, l0 = 0.0f, l1 = 0.0f;
    float oacc[16][4];
#pragma unroll
    for (int ni = 0; ni < 16; ni++)
#pragma unroll
        for (int r = 0; r < 4; r++) oacc[ni][r] = 0.0f;

    const float scale = 0.08838834764831845f;
    const int nkv = (q0 + AQ_BQ) / 32;
    const int row0g = q0 + w * 16 + lm;
    const int row1g = row0g + 8;
    const int wlast = q0 + w * 16 + 15;   // last q-row this warp owns
    const int wfirst = q0 + w * 16;

    for (int kt = 0; kt < nkv; kt++) {
        const int kv0 = kt * 32;
        __syncthreads();
        // ---- load K,V tiles (32x128) into B-fragment layouts ----
#pragma unroll
        for (int it = 0; it < 4; it++) {
            int idx = tid + it * 256;
            int r = idx >> 5;             // 0..31
            int c4 = (idx & 31) * 4;
            size_t goff = (size_t)(kv0 + r) * D_ + c4;
            float4 k4 = *(const float4*)(Kg + goff);
            float4 v4 = *(const float4*)(Vg + goff);
            int dkt = c4 >> 3;
            int rhK = ((c4 & 7) >= 4) ? 1 : 0;
            {
                float* tp = &Ks[((r >> 3) * 16 + dkt) * 68 + rhK];
                int lf = (r & 7) << 2;
                tp[(lf + 0) * 2] = to_tf32(k4.x);
                tp[(lf + 1) * 2] = to_tf32(k4.y);
                tp[(lf + 2) * 2] = to_tf32(k4.z);
                tp[(lf + 3) * 2] = to_tf32(k4.w);
            }
            {
                int rhV = ((r & 7) >= 4) ? 1 : 0;
                float* tp = &Vs[((r >> 3) * 16 + dkt) * 68 + rhV];
                int dbase = c4 & 7;
                int kl = r & 3;
                tp[((dbase + 0) * 4 + kl) * 2] = to_tf32(v4.x);
                tp[((dbase + 1) * 4 + kl) * 2] = to_tf32(v4.y);
                tp[((dbase + 2) * 4 + kl) * 2] = to_tf32(v4.z);
                tp[((dbase + 3) * 4 + kl) * 2] = to_tf32(v4.w);
            }
        }
        __syncthreads();

        if (kv0 > wlast) continue;   // tile fully masked for this warp

        float sacc[4][4];
#pragma unroll
        for (int ni = 0; ni < 4; ni++)
#pragma unroll
            for (int r = 0; r < 4; r++) sacc[ni][r] = 0.0f;

#pragma unroll
        for (int dk = 0; dk < 16; dk++) {
            float afr[4];
            *(float4*)afr = *(float4*)&Qs[(w * 16 + dk) * 132 + lane * 4];
#pragma unroll
            for (int ni = 0; ni < 4; ni++) {
                float bfr[2];
                *(float2*)bfr = *(float2*)&Ks[(ni * 16 + dk) * 68 + lane * 2];
                mma_tf32(sacc[ni], afr, bfr);
            }
        }

        const bool needMask = (kv0 + 31 > wfirst);
#pragma unroll
        for (int ni = 0; ni < 4; ni++) {
            int c0 = kv0 + ni * 8 + 2 * lk;
#pragma unroll
            for (int r = 0; r < 4; r++) sacc[ni][r] *= scale;
            if (needMask) {
                if (c0     > row0g) sacc[ni][0] = -1e30f;
                if (c0 + 1 > row0g) sacc[ni][1] = -1e30f;
                if (c0     > row1g) sacc[ni][2] = -1e30f;
                if (c0 + 1 > row1g) sacc[ni][3] = -1e30f;
            }
        }

        float rmax0 = -1e30f, rmax1 = -1e30f;
#pragma unroll
        for (int ni = 0; ni < 4; ni++) {
            rmax0 = fmaxf(rmax0, fmaxf(sacc[ni][0], sacc[ni][1]));
            rmax1 = fmaxf(rmax1, fmaxf(sacc[ni][2], sacc[ni][3]));
        }
        rmax0 = fmaxf(rmax0, __shfl_xor_sync(0xffffffffu, rmax0, 1));
        rmax0 = fmaxf(rmax0, __shfl_xor_sync(0xffffffffu, rmax0, 2));
        rmax1 = fmaxf(rmax1, __shfl_xor_sync(0xffffffffu, rmax1, 1));
        rmax1 = fmaxf(rmax1, __shfl_xor_sync(0xffffffffu, rmax1, 2));
        float mn0 = fmaxf(m0, rmax0);
        float mn1 = fmaxf(m1, rmax1);
        float al0 = __expf(m0 - mn0);
        float al1 = __expf(m1 - mn1);
        float rs0 = 0.0f, rs1 = 0.0f;
#pragma unroll
        for (int ni = 0; ni < 4; ni++) {
            sacc[ni][0] = __expf(sacc[ni][0] - mn0);
            sacc[ni][1] = __expf(sacc[ni][1] - mn0);
            sacc[ni][2] = __expf(sacc[ni][2] - mn1);
            sacc[ni][3] = __expf(sacc[ni][3] - mn1);
            rs0 += sacc[ni][0] + sacc[ni][1];
            rs1 += sacc[ni][2] + sacc[ni][3];
        }
        rs0 += __shfl_xor_sync(0xffffffffu, rs0, 1);
        rs0 += __shfl_xor_sync(0xffffffffu, rs0, 2);
        rs1 += __shfl_xor_sync(0xffffffffu, rs1, 1);
        rs1 += __shfl_xor_sync(0xffffffffu, rs1, 2);
        l0 = l0 * al0 + rs0;
        l1 = l1 * al1 + rs1;
        m0 = mn0;
        m1 = mn1;
#pragma unroll
        for (int ni = 0; ni < 16; ni++) {
            oacc[ni][0] *= al0; oacc[ni][1] *= al0;
            oacc[ni][2] *= al1; oacc[ni][3] *= al1;
        }

#pragma unroll
        for (int ni = 0; ni < 4; ni++) {
            float* tp = &Ps[(w * 4 + ni) * 132];
            int c0 = 2 * lk;
            int lf0 = (lm << 2) | (c0 & 3);
            int rh0 = (c0 >= 4) ? 2 : 0;
            tp[lf0 * 4 + rh0]     = to_tf32(sacc[ni][0]);
            tp[lf0 * 4 + rh0 + 1] = to_tf32(sacc[ni][2]);
            int c1 = 2 * lk + 1;
            int lf1 = (lm << 2) | (c1 & 3);
            int rh1 = (c1 >= 4) ? 2 : 0;
            tp[lf1 * 4 + rh1]     = to_tf32(sacc[ni][1]);
            tp[lf1 * 4 + rh1 + 1] = to_tf32(sacc[ni][3]);
        }
        __syncwarp();

#pragma unroll
        for (int kt2 = 0; kt2 < 4; kt2++) {
            float afr[4];
            *(float4*)afr = *(float4*)&Ps[(w * 4 + kt2) * 132 + lane * 4];
#pragma unroll
            for (int ni = 0; ni < 16; ni++) {
                float bfr[2];
                *(float2*)bfr = *(float2*)&Vs[(kt2 * 16 + ni) * 68 + lane * 2];
                mma_tf32(oacc[ni], afr, bfr);
            }
        }
    }

    float inv0 = 1.0f / l0;
    float inv1 = 1.0f / l1;
    float* out0 = g_attn + ((size_t)(b * T_ + row0g)) * C_ + h * D_;
    float* out1 = g_attn + ((size_t)(b * T_ + row1g)) * C_ + h * D_;
#pragma unroll
    for (int ni = 0; ni < 16; ni++) {
        int col = ni * 8 + 2 * lk;
        *(float2*)(out0 + col) = make_float2(to_tf32(oacc[ni][0] * inv0),
                                             to_tf32(oacc[ni][1] * inv0));
        *(float2*)(out1 + col) = make_float2(to_tf32(oacc[ni][2] * inv1),
                                             to_tf32(oacc[ni][3] * inv1));
    }
}

// ---------------- launch -------------------------------------------------------
extern "C" void kernel_launch(void* const* d_in, const int* in_sizes, int n_in,
                              void* d_out, int out_size)
{
    const float* x      = (const float*)d_in[0];
    const float* cosg   = (const float*)d_in[1];
    const float* sing   = (const float*)d_in[2];
    const float* W_qkv  = (const float*)d_in[3];
    const float* W_proj = (const float*)d_in[4];
    float* out = (float*)d_out;

    float* qkv;    cudaGetSymbolAddress((void**)&qkv,    g_qkv);
    float* Qb;     cudaGetSymbolAddress((void**)&Qb,     g_Q);
    float* Kb;     cudaGetSymbolAddress((void**)&Kb,     g_K);
    float* Vb;     cudaGetSymbolAddress((void**)&Vb,     g_V);
    float* attn;   cudaGetSymbolAddress((void**)&attn,   g_attn);
    float* xc;     cudaGetSymbolAddress((void**)&xc,     g_xc);
    float* wqkvC;  cudaGetSymbolAddress((void**)&wqkvC,  g_wqkvC);
    float* wprojC; cudaGetSymbolAddress((void**)&wprojC, g_wprojC);

    const int M = B_ * T_;   // 4096

    cudaFuncSetAttribute(gemm_v4_kernel,
                         cudaFuncAttributeMaxDynamicSharedMemorySize, V4_SMEM_BYTES);
    cudaFuncSetAttribute(attn_mma_kernel,
                         cudaFuncAttributeMaxDynamicSharedMemorySize,
                         ATTN_SMEM_FLOATS * sizeof(float));

    // 0) tf32-round x / W_qkv / W_proj in gmem
    {
        int n4x = (M * C_) / 4;
        convert_tf32_kernel<<<(n4x + 255) / 256, 256>>>(x, xc, n4x);
        int n4q = (C_ * 3 * C_) / 4;
        convert_tf32_kernel<<<(n4q + 255) / 256, 256>>>(W_qkv, wqkvC, n4q);
        int n4p = (C_ * C_) / 4;
        convert_tf32_kernel<<<(n4p + 255) / 256, 256>>>(W_proj, wprojC, n4p);
    }

    // 1) qkv = xc @ wqkvC
    {
        dim3 grid(3 * C_ / V4_BN, M / V4_BM);   // (48, 32)
        gemm_v4_kernel<<<grid, 256, V4_SMEM_BYTES>>>(xc, wqkvC, qkv, M, 3 * C_, C_);
    }
    // 2) RoPE + split
    {
        dim3 grid(H_, T_, B_);
        rope_split_kernel<<<grid, 128>>>(qkv, cosg, sing, Qb, Kb, Vb);
    }
    // 3) attention -> g_attn (tf32-rounded), BQ=128
    {
        dim3 grid(T_ / AQ_BQ, B_ * H_);         // (16, 32)
        attn_mma_kernel<<<grid, 256, ATTN_SMEM_FLOATS * sizeof(float)>>>(Qb, Kb, Vb);
    }
    // 4) out = attn @ wprojC
    {
        dim3 grid(C_ / V4_BN, M / V4_BM);       // (16, 32)
        gemm_v4_kernel<<<grid, 256, V4_SMEM_BYTES>>>(attn, wprojC, out, M, C_, C_);
    }
}

// round 9
// speedup vs baseline: 4.5622x; 1.0264x over previous
#include <cuda_runtime.h>
#include <cstdio>
#include <cstdint>

#define B_ 2
#define T_ 2048
#define C_ 2048
#define H_ 16
#define D_ 128

// ---------------- scratch (device globals: no runtime allocation) ----------------
__device__ float g_qkv[(size_t)B_ * T_ * 3 * C_];
__device__ float g_Q[(size_t)B_ * H_ * T_ * D_];
__device__ float g_K[(size_t)B_ * H_ * T_ * D_];
__device__ float g_V[(size_t)B_ * H_ * T_ * D_];
__device__ float g_attn[(size_t)B_ * T_ * C_];
__device__ float g_xc[(size_t)B_ * T_ * C_];          // tf32-rounded x
__device__ float g_wqkvC[(size_t)C_ * 3 * C_];        // tf32-rounded W_qkv
__device__ float g_wprojC[(size_t)C_ * C_];           // tf32-rounded W_proj

// ---------------- helpers -------------------------------------------------------
__device__ __forceinline__ float to_tf32(float x) {
    unsigned u;
    asm("cvt.rna.tf32.f32 %0, %1;" : "=r"(u) : "f"(x));
    return __uint_as_float(u);
}

__device__ __forceinline__ void mma_tf32(float c[4], const float a[4], const float b[2]) {
    asm volatile(
        "mma.sync.aligned.m16n8k8.row.col.f32.tf32.tf32.f32 "
        "{%0,%1,%2,%3}, {%4,%5,%6,%7}, {%8,%9}, {%0,%1,%2,%3};"
        : "+f"(c[0]), "+f"(c[1]), "+f"(c[2]), "+f"(c[3])
        : "r"(__float_as_uint(a[0])), "r"(__float_as_uint(a[1])),
          "r"(__float_as_uint(a[2])), "r"(__float_as_uint(a[3])),
          "r"(__float_as_uint(b[0])), "r"(__float_as_uint(b[1])));
}

__device__ __forceinline__ uint32_t smem_u32(const void* p) {
    uint32_t a;
    asm("{ .reg .u64 t; cvta.to.shared.u64 t, %1; cvt.u32.u64 %0, t; }" : "=r"(a) : "l"(p));
    return a;
}

#define CP_ASYNC16(dst, src) \
    asm volatile("cp.async.cg.shared.global [%0], [%1], 16;" :: "r"(dst), "l"(src) : "memory")
#define CP_COMMIT() asm volatile("cp.async.commit_group;" ::: "memory")

// ================= GEMM v4: cp.async, BK=32, 3 stages, 128x128, warp 64x32 ======
#define V4_BM 128
#define V4_BN 128
#define V4_BK 32
#define V4_APAD 36
#define V4_BPAD 136
#define V4_AFLOATS (V4_BM * V4_APAD)          // 4608
#define V4_BFLOATS (V4_BK * V4_BPAD)          // 4352
#define V4_STAGEF (V4_AFLOATS + V4_BFLOATS)   // 8960 floats = 35840 B
#define V4_NST 3
#define V4_SMEM_BYTES (V4_NST * V4_STAGEF * 4)  // 107520

__global__ __launch_bounds__(256, 2) void gemm_v4_kernel(
    const float* __restrict__ A, const float* __restrict__ W, float* __restrict__ Cm,
    int M, int N, int K)
{
    extern __shared__ float sm[];

    const int tid = threadIdx.x;
    const int warp = tid >> 5;
    const int lane = tid & 31;
    const int lm = lane >> 2;
    const int lk = lane & 3;

    const int m0 = blockIdx.y * V4_BM;
    const int n0 = blockIdx.x * V4_BN;
    const int wm = (warp >> 2) * 64;
    const int wn = (warp & 3) * 32;

    const uint32_t smb = smem_u32(sm);

    float acc[4][4][4];
#pragma unroll
    for (int mi = 0; mi < 4; mi++)
#pragma unroll
        for (int ni = 0; ni < 4; ni++)
#pragma unroll
            for (int r = 0; r < 4; r++) acc[mi][ni][r] = 0.0f;

    auto load_stage = [&](int s) {
        const int k0 = s * V4_BK;
        const uint32_t base = smb + (uint32_t)((s % V4_NST) * V4_STAGEF * 4);
#pragma unroll
        for (int i = 0; i < 4; i++) {
            int id = tid + i * 256;
            int r = id >> 3, c = id & 7;
            uint32_t dst = base + (uint32_t)(r * (V4_APAD * 4) + c * 16);
            const float* src = A + (size_t)(m0 + r) * K + k0 + c * 4;
            CP_ASYNC16(dst, src);
        }
        const uint32_t bbase = base + V4_AFLOATS * 4;
#pragma unroll
        for (int i = 0; i < 4; i++) {
            int id = tid + i * 256;
            int k = id >> 5, n4 = id & 31;
            uint32_t dst = bbase + (uint32_t)(k * (V4_BPAD * 4) + n4 * 16);
            const float* src = W + (size_t)(k0 + k) * N + n0 + n4 * 4;
            CP_ASYNC16(dst, src);
        }
        CP_COMMIT();
    };

    const int nst = K / V4_BK;   // 64
    load_stage(0);
    load_stage(1);

    for (int ks = 0; ks < nst; ks++) {
        asm volatile("cp.async.wait_group %0;" :: "n"(1) : "memory");
        __syncthreads();

        const float* As = sm + (size_t)(ks % V4_NST) * V4_STAGEF;
        const float* Bs = As + V4_AFLOATS;

#pragma unroll
        for (int kk = 0; kk < V4_BK; kk += 8) {
            float afr[4][4];
#pragma unroll
            for (int mi = 0; mi < 4; mi++) {
                int row = wm + mi * 16 + lm;
                afr[mi][0] = As[row * V4_APAD + kk + lk];
                afr[mi][1] = As[(row + 8) * V4_APAD + kk + lk];
                afr[mi][2] = As[row * V4_APAD + kk + lk + 4];
                afr[mi][3] = As[(row + 8) * V4_APAD + kk + lk + 4];
            }
            float bfr[4][2];
#pragma unroll
            for (int ni = 0; ni < 4; ni++) {
                int col = wn + ni * 8 + lm;
                bfr[ni][0] = Bs[(kk + lk) * V4_BPAD + col];
                bfr[ni][1] = Bs[(kk + lk + 4) * V4_BPAD + col];
            }
#pragma unroll
            for (int mi = 0; mi < 4; mi++)
#pragma unroll
                for (int ni = 0; ni < 4; ni++)
                    mma_tf32(acc[mi][ni], afr[mi], bfr[ni]);
        }

        if (ks + 2 < nst) load_stage(ks + 2);
        else CP_COMMIT();
    }

#pragma unroll
    for (int mi = 0; mi < 4; mi++) {
#pragma unroll
        for (int ni = 0; ni < 4; ni++) {
            int gr = m0 + wm + mi * 16 + lm;
            int gc = n0 + wn + ni * 8 + lk * 2;
            float* p0 = Cm + (size_t)gr * N + gc;
            float* p1 = Cm + (size_t)(gr + 8) * N + gc;
            *(float2*)p0 = make_float2(acc[mi][ni][0], acc[mi][ni][1]);
            *(float2*)p1 = make_float2(acc[mi][ni][2], acc[mi][ni][3]);
        }
    }
}

// ---------------- pre-pass: tf32 rounding ---------------------------------------
__global__ __launch_bounds__(256) void convert_tf32_kernel(
    const float* __restrict__ src, float* __restrict__ dst, int n4)
{
    int i = blockIdx.x * blockDim.x + threadIdx.x;
    if (i < n4) {
        float4 v = *(const float4*)(src + (size_t)i * 4);
        v.x = to_tf32(v.x); v.y = to_tf32(v.y);
        v.z = to_tf32(v.z); v.w = to_tf32(v.w);
        *(float4*)(dst + (size_t)i * 4) = v;
    }
}

// ---------------- RoPE + split/transpose ----------------------------------------
__global__ __launch_bounds__(128) void rope_split_kernel(
    const float* __restrict__ qkv, const float* __restrict__ cosg,
    const float* __restrict__ sing,
    float* __restrict__ Q, float* __restrict__ K, float* __restrict__ V)
{
    const int h = blockIdx.x;
    const int t = blockIdx.y;
    const int b = blockIdx.z;
    const int d = threadIdx.x;

    const float* base = qkv + ((size_t)(b * T_ + t)) * (3 * C_) + h * D_;
    const size_t outBase = ((size_t)((b * H_ + h) * T_ + t)) * D_;

    V[outBase + d] = base[2 * C_ + d];

    if (d < D_ / 2) {
        const float c = cosg[t * (D_ / 2) + d];
        const float s = sing[t * (D_ / 2) + d];
        float q1 = base[d];
        float q2 = base[d + D_ / 2];
        Q[outBase + d]          = q1 * c - q2 * s;
        Q[outBase + d + D_ / 2] = q1 * s + q2 * c;
        float k1 = base[C_ + d];
        float k2 = base[C_ + d + D_ / 2];
        K[outBase + d]          = k1 * c - k2 * s;
        K[outBase + d + D_ / 2] = k1 * s + k2 * c;
    }
}

// ---------------- tf32 MMA flash attention v2: Q in registers -------------------
// BQ=64 (4 warps x 16 rows), BKV=32. Smem: K,V B-frag tiles + per-warp P tiles.
#define KS_FLOATS (64 * 68)
#define VS_FLOATS (64 * 68)
#define PS_FLOATS (16 * 132)
#define ATTN_SMEM_FLOATS (KS_FLOATS + VS_FLOATS + PS_FLOATS)   // 35.2 KB

__global__ __launch_bounds__(128, 2) void attn_mma_kernel(
    const float* __restrict__ Q, const float* __restrict__ K,
    const float* __restrict__ V)
{
    extern __shared__ float sm[];
    float* Ks = sm;
    float* Vs = Ks + KS_FLOATS;
    float* Ps = Vs + VS_FLOATS;

    const int qb = blockIdx.x;
    const int bh = blockIdx.y;
    const int b = bh >> 4;
    const int h = bh & 15;
    const int tid = threadIdx.x;
    const int w = tid >> 5;
    const int lane = tid & 31;
    const int lm = lane >> 2;
    const int lk = lane & 3;
    const int q0 = qb * 64;

    const float* Qg = Q + ((size_t)bh * T_ + q0) * D_;
    const float* Kg = K + (size_t)bh * T_ * D_;
    const float* Vg = V + (size_t)bh * T_ * D_;

    const int row0g = q0 + w * 16 + lm;
    const int row1g = row0g + 8;

    // ---- Q fragments straight into registers (tf32-rounded), 16 dk-tiles ----
    float qfr[16][4];
    {
        const float* q0p = Qg + (size_t)(w * 16 + lm) * D_;
        const float* q1p = q0p + 8 * D_;
#pragma unroll
        for (int dk = 0; dk < 16; dk++) {
            int col = dk * 8 + lk;
            qfr[dk][0] = to_tf32(q0p[col]);
            qfr[dk][1] = to_tf32(q1p[col]);
            qfr[dk][2] = to_tf32(q0p[col + 4]);
            qfr[dk][3] = to_tf32(q1p[col + 4]);
        }
    }

    float m0 = -1e30f, m1 = -1e30f, l0 = 0.0f, l1 = 0.0f;
    float oacc[16][4];
#pragma unroll
    for (int ni = 0; ni < 16; ni++)
#pragma unroll
        for (int r = 0; r < 4; r++) oacc[ni][r] = 0.0f;

    const float scale = 0.08838834764831845f;
    const int nkv = (q0 + 64) / 32;

    for (int kt = 0; kt < nkv; kt++) {
        const int kv0 = kt * 32;
        __syncthreads();
        // ---- load K,V tiles (32x128) into B-fragment layouts ----
#pragma unroll
        for (int it = 0; it < 8; it++) {
            int idx = tid + it * 128;
            int r = idx >> 5;
            int c4 = (idx & 31) * 4;
            size_t goff = (size_t)(kv0 + r) * D_ + c4;
            float4 k4 = *(const float4*)(Kg + goff);
            float4 v4 = *(const float4*)(Vg + goff);
            int dkt = c4 >> 3;
            int rhK = ((c4 & 7) >= 4) ? 1 : 0;
            {
                float* tp = &Ks[((r >> 3) * 16 + dkt) * 68 + rhK];
                int lf = (r & 7) << 2;
                tp[(lf + 0) * 2] = to_tf32(k4.x);
                tp[(lf + 1) * 2] = to_tf32(k4.y);
                tp[(lf + 2) * 2] = to_tf32(k4.z);
                tp[(lf + 3) * 2] = to_tf32(k4.w);
            }
            {
                int rhV = ((r & 7) >= 4) ? 1 : 0;
                float* tp = &Vs[((r >> 3) * 16 + dkt) * 68 + rhV];
                int dbase = c4 & 7;
                int kl = r & 3;
                tp[((dbase + 0) * 4 + kl) * 2] = to_tf32(v4.x);
                tp[((dbase + 1) * 4 + kl) * 2] = to_tf32(v4.y);
                tp[((dbase + 2) * 4 + kl) * 2] = to_tf32(v4.z);
                tp[((dbase + 3) * 4 + kl) * 2] = to_tf32(v4.w);
            }
        }
        __syncthreads();

        // ---- S = Q @ K^T (A from registers) ----
        float sacc[4][4];
#pragma unroll
        for (int ni = 0; ni < 4; ni++)
#pragma unroll
            for (int r = 0; r < 4; r++) sacc[ni][r] = 0.0f;

#pragma unroll
        for (int dk = 0; dk < 16; dk++) {
#pragma unroll
            for (int ni = 0; ni < 4; ni++) {
                float bfr[2];
                *(float2*)bfr = *(float2*)&Ks[(ni * 16 + dk) * 68 + lane * 2];
                mma_tf32(sacc[ni], qfr[dk], bfr);
            }
        }

        const bool needMask = (kt >= 2 * qb);
#pragma unroll
        for (int ni = 0; ni < 4; ni++) {
            int c0 = kv0 + ni * 8 + 2 * lk;
#pragma unroll
            for (int r = 0; r < 4; r++) sacc[ni][r] *= scale;
            if (needMask) {
                if (c0     > row0g) sacc[ni][0] = -1e30f;
                if (c0 + 1 > row0g) sacc[ni][1] = -1e30f;
                if (c0     > row1g) sacc[ni][2] = -1e30f;
                if (c0 + 1 > row1g) sacc[ni][3] = -1e30f;
            }
        }

        // ---- online softmax ----
        float rmax0 = -1e30f, rmax1 = -1e30f;
#pragma unroll
        for (int ni = 0; ni < 4; ni++) {
            rmax0 = fmaxf(rmax0, fmaxf(sacc[ni][0], sacc[ni][1]));
            rmax1 = fmaxf(rmax1, fmaxf(sacc[ni][2], sacc[ni][3]));
        }
        rmax0 = fmaxf(rmax0, __shfl_xor_sync(0xffffffffu, rmax0, 1));
        rmax0 = fmaxf(rmax0, __shfl_xor_sync(0xffffffffu, rmax0, 2));
        rmax1 = fmaxf(rmax1, __shfl_xor_sync(0xffffffffu, rmax1, 1));
        rmax1 = fmaxf(rmax1, __shfl_xor_sync(0xffffffffu, rmax1, 2));
        float mn0 = fmaxf(m0, rmax0);
        float mn1 = fmaxf(m1, rmax1);
        float al0 = __expf(m0 - mn0);
        float al1 = __expf(m1 - mn1);
        float rs0 = 0.0f, rs1 = 0.0f;
#pragma unroll
        for (int ni = 0; ni < 4; ni++) {
            sacc[ni][0] = __expf(sacc[ni][0] - mn0);
            sacc[ni][1] = __expf(sacc[ni][1] - mn0);
            sacc[ni][2] = __expf(sacc[ni][2] - mn1);
            sacc[ni][3] = __expf(sacc[ni][3] - mn1);
            rs0 += sacc[ni][0] + sacc[ni][1];
            rs1 += sacc[ni][2] + sacc[ni][3];
        }
        rs0 += __shfl_xor_sync(0xffffffffu, rs0, 1);
        rs0 += __shfl_xor_sync(0xffffffffu, rs0, 2);
        rs1 += __shfl_xor_sync(0xffffffffu, rs1, 1);
        rs1 += __shfl_xor_sync(0xffffffffu, rs1, 2);
        l0 = l0 * al0 + rs0;
        l1 = l1 * al1 + rs1;
        m0 = mn0;
        m1 = mn1;
#pragma unroll
        for (int ni = 0; ni < 16; ni++) {
            oacc[ni][0] *= al0; oacc[ni][1] *= al0;
            oacc[ni][2] *= al1; oacc[ni][3] *= al1;
        }

        // ---- store P to per-warp A-frag tiles ----
#pragma unroll
        for (int ni = 0; ni < 4; ni++) {
            float* tp = &Ps[(w * 4 + ni) * 132];
            int c0 = 2 * lk;
            int lf0 = (lm << 2) | (c0 & 3);
            int rh0 = (c0 >= 4) ? 2 : 0;
            tp[lf0 * 4 + rh0]     = to_tf32(sacc[ni][0]);
            tp[lf0 * 4 + rh0 + 1] = to_tf32(sacc[ni][2]);
            int c1 = 2 * lk + 1;
            int lf1 = (lm << 2) | (c1 & 3);
            int rh1 = (c1 >= 4) ? 2 : 0;
            tp[lf1 * 4 + rh1]     = to_tf32(sacc[ni][1]);
            tp[lf1 * 4 + rh1 + 1] = to_tf32(sacc[ni][3]);
        }
        __syncwarp();

        // ---- O += P @ V ----
#pragma unroll
        for (int kt2 = 0; kt2 < 4; kt2++) {
            float afr[4];
            *(float4*)afr = *(float4*)&Ps[(w * 4 + kt2) * 132 + lane * 4];
#pragma unroll
            for (int ni = 0; ni < 16; ni++) {
                float bfr[2];
                *(float2*)bfr = *(float2*)&Vs[(kt2 * 16 + ni) * 68 + lane * 2];
                mma_tf32(oacc[ni], afr, bfr);
            }
        }
    }

    float inv0 = 1.0f / l0;
    float inv1 = 1.0f / l1;
    float* out0 = g_attn + ((size_t)(b * T_ + row0g)) * C_ + h * D_;
    float* out1 = g_attn + ((size_t)(b * T_ + row1g)) * C_ + h * D_;
#pragma unroll
    for (int ni = 0; ni < 16; ni++) {
        int col = ni * 8 + 2 * lk;
        *(float2*)(out0 + col) = make_float2(to_tf32(oacc[ni][0] * inv0),
                                             to_tf32(oacc[ni][1] * inv0));
        *(float2*)(out1 + col) = make_float2(to_tf32(oacc[ni][2] * inv1),
                                             to_tf32(oacc[ni][3] * inv1));
    }
}

// ---------------- launch -------------------------------------------------------
extern "C" void kernel_launch(void* const* d_in, const int* in_sizes, int n_in,
                              void* d_out, int out_size)
{
    const float* x      = (const float*)d_in[0];
    const float* cosg   = (const float*)d_in[1];
    const float* sing   = (const float*)d_in[2];
    const float* W_qkv  = (const float*)d_in[3];
    const float* W_proj = (const float*)d_in[4];
    float* out = (float*)d_out;

    float* qkv;    cudaGetSymbolAddress((void**)&qkv,    g_qkv);
    float* Qb;     cudaGetSymbolAddress((void**)&Qb,     g_Q);
    float* Kb;     cudaGetSymbolAddress((void**)&Kb,     g_K);
    float* Vb;     cudaGetSymbolAddress((void**)&Vb,     g_V);
    float* attn;   cudaGetSymbolAddress((void**)&attn,   g_attn);
    float* xc;     cudaGetSymbolAddress((void**)&xc,     g_xc);
    float* wqkvC;  cudaGetSymbolAddress((void**)&wqkvC,  g_wqkvC);
    float* wprojC; cudaGetSymbolAddress((void**)&wprojC, g_wprojC);

    const int M = B_ * T_;   // 4096

    cudaFuncSetAttribute(gemm_v4_kernel,
                         cudaFuncAttributeMaxDynamicSharedMemorySize, V4_SMEM_BYTES);
    cudaFuncSetAttribute(attn_mma_kernel,
                         cudaFuncAttributeMaxDynamicSharedMemorySize,
                         ATTN_SMEM_FLOATS * sizeof(float));

    // 0) tf32-round x / W_qkv / W_proj in gmem
    {
        int n4x = (M * C_) / 4;
        convert_tf32_kernel<<<(n4x + 255) / 256, 256>>>(x, xc, n4x);
        int n4q = (C_ * 3 * C_) / 4;
        convert_tf32_kernel<<<(n4q + 255) / 256, 256>>>(W_qkv, wqkvC, n4q);
        int n4p = (C_ * C_) / 4;
        convert_tf32_kernel<<<(n4p + 255) / 256, 256>>>(W_proj, wprojC, n4p);
    }

    // 1) qkv = xc @ wqkvC
    {
        dim3 grid(3 * C_ / V4_BN, M / V4_BM);   // (48, 32)
        gemm_v4_kernel<<<grid, 256, V4_SMEM_BYTES>>>(xc, wqkvC, qkv, M, 3 * C_, C_);
    }
    // 2) RoPE + split
    {
        dim3 grid(H_, T_, B_);
        rope_split_kernel<<<grid, 128>>>(qkv, cosg, sing, Qb, Kb, Vb);
    }
    // 3) attention -> g_attn (tf32-rounded), Q in registers
    {
        dim3 grid(T_ / 64, B_ * H_);            // (32, 32)
        attn_mma_kernel<<<grid, 128, ATTN_SMEM_FLOATS * sizeof(float)>>>(Qb, Kb, Vb);
    }
    // 4) out = attn @ wprojC
    {
        dim3 grid(C_ / V4_BN, M / V4_BM);       // (16, 32)
        gemm_v4_kernel<<<grid, 256, V4_SMEM_BYTES>>>(attn, wprojC, out, M, C_, C_);
    }
}

// round 10
// speedup vs baseline: 4.6295x; 1.0147x over previous
#include <cuda_runtime.h>
#include <cstdio>
#include <cstdint>

#define B_ 2
#define T_ 2048
#define C_ 2048
#define H_ 16
#define D_ 128

// ---------------- scratch (device globals: no runtime allocation) ----------------
__device__ float g_qkv[(size_t)B_ * T_ * 3 * C_];
__device__ float g_Q[(size_t)B_ * H_ * T_ * D_];
__device__ float g_K[(size_t)B_ * H_ * T_ * D_];
__device__ float g_V[(size_t)B_ * H_ * T_ * D_];
__device__ float g_attn[(size_t)B_ * T_ * C_];        // PACKED-A layout (pairs m,m+8)
__device__ float g_xc[(size_t)B_ * T_ * C_];          // packed-A tf32 x
__device__ float g_wqkvC[(size_t)C_ * 3 * C_];        // packed-B tf32 W_qkv
__device__ float g_wprojC[(size_t)C_ * C_];           // packed-B tf32 W_proj

// Packed-A: element (m,k) at [((m>>4)*8 + (m&7))*K + k]*2 + ((m>>3)&1)
// Packed-B: element (k,n) at [((k>>3)*4 + (k&3))*N + n]*2 + ((k>>2)&1)

// ---------------- helpers -------------------------------------------------------
__device__ __forceinline__ float to_tf32(float x) {
    unsigned u;
    asm("cvt.rna.tf32.f32 %0, %1;" : "=r"(u) : "f"(x));
    return __uint_as_float(u);
}

__device__ __forceinline__ void mma_tf32(float c[4], const float a[4], const float b[2]) {
    asm volatile(
        "mma.sync.aligned.m16n8k8.row.col.f32.tf32.tf32.f32 "
        "{%0,%1,%2,%3}, {%4,%5,%6,%7}, {%8,%9}, {%0,%1,%2,%3};"
        : "+f"(c[0]), "+f"(c[1]), "+f"(c[2]), "+f"(c[3])
        : "r"(__float_as_uint(a[0])), "r"(__float_as_uint(a[1])),
          "r"(__float_as_uint(a[2])), "r"(__float_as_uint(a[3])),
          "r"(__float_as_uint(b[0])), "r"(__float_as_uint(b[1])));
}

__device__ __forceinline__ uint32_t smem_u32(const void* p) {
    uint32_t a;
    asm("{ .reg .u64 t; cvta.to.shared.u64 t, %1; cvt.u32.u64 %0, t; }" : "=r"(a) : "l"(p));
    return a;
}

#define CP_ASYNC16(dst, src) \
    asm volatile("cp.async.cg.shared.global [%0], [%1], 16;" :: "r"(dst), "l"(src) : "memory")
#define CP_COMMIT() asm volatile("cp.async.commit_group;" ::: "memory")

// ============ GEMM v5: packed operands, LDS.64 frags, BK=32, 3 stages ===========
// A smem: [64 pairs][32 k][2]  stride 72 floats  (banks 8*lm+2*lk: conflict-free)
// B smem: [16 kp][128 n][2]    stride 264 floats (banks 8*lk+2*lm: conflict-free)
#define V5_BM 128
#define V5_BN 128
#define V5_BK 32
#define V5_ASTR 72
#define V5_BSTR 264
#define V5_AFLOATS (64 * V5_ASTR)             // 4608
#define V5_BFLOATS (16 * V5_BSTR)             // 4224
#define V5_STAGEF (V5_AFLOATS + V5_BFLOATS)   // 8832 floats = 35328 B
#define V5_NST 3
#define V5_SMEM_BYTES (V5_NST * V5_STAGEF * 4)  // 105984

__global__ __launch_bounds__(256, 2) void gemm_v5_kernel(
    const float* __restrict__ Ap, const float* __restrict__ Bp, float* __restrict__ Cm,
    int M, int N, int K)
{
    extern __shared__ float sm[];

    const int tid = threadIdx.x;
    const int warp = tid >> 5;
    const int lane = tid & 31;
    const int lm = lane >> 2;
    const int lk = lane & 3;

    const int m0 = blockIdx.y * V5_BM;
    const int n0 = blockIdx.x * V5_BN;
    const int wm = (warp >> 2) * 64;
    const int wn = (warp & 3) * 32;

    const uint32_t smb = smem_u32(sm);

    float acc[4][4][4];
#pragma unroll
    for (int mi = 0; mi < 4; mi++)
#pragma unroll
        for (int ni = 0; ni < 4; ni++)
#pragma unroll
            for (int r = 0; r < 4; r++) acc[mi][ni][r] = 0.0f;

    auto load_stage = [&](int s) {
        const int k0 = s * V5_BK;
        const uint32_t base = smb + (uint32_t)((s % V5_NST) * V5_STAGEF * 4);
        // A: 1024 chunks of 16B: p = id>>4 (0..63), kc = id&15 (k-pairs of 2)
#pragma unroll
        for (int i = 0; i < 4; i++) {
            int id = tid + i * 256;
            int p = id >> 4, kc = id & 15;
            uint32_t dst = base + (uint32_t)((p * V5_ASTR + kc * 4) * 4);
            const float* src = Ap + ((size_t)(m0 / 2 + p) * K + k0 + kc * 2) * 2;
            CP_ASYNC16(dst, src);
        }
        // B: 1024 chunks: kp = id>>6 (0..15), nc = id&63 (n-pairs of 2)
        const uint32_t bbase = base + V5_AFLOATS * 4;
#pragma unroll
        for (int i = 0; i < 4; i++) {
            int id = tid + i * 256;
            int kp = id >> 6, nc = id & 63;
            uint32_t dst = bbase + (uint32_t)((kp * V5_BSTR + nc * 4) * 4);
            const float* src = Bp + ((size_t)(k0 / 2 + kp) * N + n0 + nc * 2) * 2;
            CP_ASYNC16(dst, src);
        }
        CP_COMMIT();
    };

    const int nst = K / V5_BK;   // 64
    load_stage(0);
    load_stage(1);

    for (int ks = 0; ks < nst; ks++) {
        asm volatile("cp.async.wait_group %0;" :: "n"(1) : "memory");
        __syncthreads();

        const float* As = sm + (size_t)(ks % V5_NST) * V5_STAGEF;
        const float* Bs = As + V5_AFLOATS;

#pragma unroll
        for (int kk = 0; kk < V5_BK; kk += 8) {
            float afr[4][4];
#pragma unroll
            for (int mi = 0; mi < 4; mi++) {
                int aw = (((wm >> 4) + mi) * 8 + lm) * V5_ASTR + (kk + lk) * 2;
                *(float2*)&afr[mi][0] = *(const float2*)&As[aw];       // {m,k},{m+8,k}
                *(float2*)&afr[mi][2] = *(const float2*)&As[aw + 8];   // {m,k+4},{m+8,k+4}
            }
            float bfr[4][2];
#pragma unroll
            for (int ni = 0; ni < 4; ni++) {
                int bw = ((kk >> 3) * 4 + lk) * V5_BSTR + (wn + ni * 8 + lm) * 2;
                *(float2*)&bfr[ni][0] = *(const float2*)&Bs[bw];       // {k,n},{k+4,n}
            }
#pragma unroll
            for (int mi = 0; mi < 4; mi++)
#pragma unroll
                for (int ni = 0; ni < 4; ni++)
                    mma_tf32(acc[mi][ni], afr[mi], bfr[ni]);
        }

        if (ks + 2 < nst) load_stage(ks + 2);
        else CP_COMMIT();
    }

    // epilogue: standard row-major C
#pragma unroll
    for (int mi = 0; mi < 4; mi++) {
#pragma unroll
        for (int ni = 0; ni < 4; ni++) {
            int gr = m0 + wm + mi * 16 + lm;
            int gc = n0 + wn + ni * 8 + lk * 2;
            float* p0 = Cm + (size_t)gr * N + gc;
            float* p1 = Cm + (size_t)(gr + 8) * N + gc;
            *(float2*)p0 = make_float2(acc[mi][ni][0], acc[mi][ni][1]);
            *(float2*)p1 = make_float2(acc[mi][ni][2], acc[mi][ni][3]);
        }
    }
}

// ---------------- pack pre-passes (tf32-round + layout) -------------------------
// A-pack: chunk c -> pair p = c/(K/2), kc = c%(K/2); rows m,(m+8); k = kc*2
__global__ __launch_bounds__(256) void pack_a_kernel(
    const float* __restrict__ src, float* __restrict__ dst, int K, int nchunk)
{
    int c = blockIdx.x * blockDim.x + threadIdx.x;
    if (c >= nchunk) return;
    int kh = K >> 1;
    int p = c / kh, kc = c - p * kh;
    int m = (p >> 3) * 16 + (p & 7);
    int k = kc * 2;
    const float* r0 = src + (size_t)m * K + k;
    const float* r1 = r0 + (size_t)8 * K;
    float4 v;
    v.x = to_tf32(r0[0]); v.y = to_tf32(r1[0]);
    v.z = to_tf32(r0[1]); v.w = to_tf32(r1[1]);
    *(float4*)(dst + (size_t)c * 4) = v;
}

// B-pack: chunk c -> kp = c/(N/2), nc = c%(N/2); rows k,(k+4); n = nc*2
__global__ __launch_bounds__(256) void pack_b_kernel(
    const float* __restrict__ src, float* __restrict__ dst, int N, int nchunk)
{
    int c = blockIdx.x * blockDim.x + threadIdx.x;
    if (c >= nchunk) return;
    int nh = N >> 1;
    int kp = c / nh, nc = c - kp * nh;
    int k = (kp >> 2) * 8 + (kp & 3);
    int n = nc * 2;
    const float* r0 = src + (size_t)k * N + n;
    const float* r1 = r0 + (size_t)4 * N;
    float4 v;
    v.x = to_tf32(r0[0]); v.y = to_tf32(r1[0]);
    v.z = to_tf32(r0[1]); v.w = to_tf32(r1[1]);
    *(float4*)(dst + (size_t)c * 4) = v;
}

// ---------------- RoPE + split/transpose ----------------------------------------
__global__ __launch_bounds__(128) void rope_split_kernel(
    const float* __restrict__ qkv, const float* __restrict__ cosg,
    const float* __restrict__ sing,
    float* __restrict__ Q, float* __restrict__ K, float* __restrict__ V)
{
    const int h = blockIdx.x;
    const int t = blockIdx.y;
    const int b = blockIdx.z;
    const int d = threadIdx.x;

    const float* base = qkv + ((size_t)(b * T_ + t)) * (3 * C_) + h * D_;
    const size_t outBase = ((size_t)((b * H_ + h) * T_ + t)) * D_;

    V[outBase + d] = base[2 * C_ + d];

    if (d < D_ / 2) {
        const float c = cosg[t * (D_ / 2) + d];
        const float s = sing[t * (D_ / 2) + d];
        float q1 = base[d];
        float q2 = base[d + D_ / 2];
        Q[outBase + d]          = q1 * c - q2 * s;
        Q[outBase + d + D_ / 2] = q1 * s + q2 * c;
        float k1 = base[C_ + d];
        float k2 = base[C_ + d + D_ / 2];
        K[outBase + d]          = k1 * c - k2 * s;
        K[outBase + d + D_ / 2] = k1 * s + k2 * c;
    }
}

// ---------------- tf32 MMA flash attention (Q in registers) ---------------------
#define KS_FLOATS (64 * 68)
#define VS_FLOATS (64 * 68)
#define PS_FLOATS (16 * 132)
#define ATTN_SMEM_FLOATS (KS_FLOATS + VS_FLOATS + PS_FLOATS)   // 35.2 KB

__global__ __launch_bounds__(128, 2) void attn_mma_kernel(
    const float* __restrict__ Q, const float* __restrict__ K,
    const float* __restrict__ V)
{
    extern __shared__ float sm[];
    float* Ks = sm;
    float* Vs = Ks + KS_FLOATS;
    float* Ps = Vs + VS_FLOATS;

    const int qb = blockIdx.x;
    const int bh = blockIdx.y;
    const int b = bh >> 4;
    const int h = bh & 15;
    const int tid = threadIdx.x;
    const int w = tid >> 5;
    const int lane = tid & 31;
    const int lm = lane >> 2;
    const int lk = lane & 3;
    const int q0 = qb * 64;

    const float* Qg = Q + ((size_t)bh * T_ + q0) * D_;
    const float* Kg = K + (size_t)bh * T_ * D_;
    const float* Vg = V + (size_t)bh * T_ * D_;

    const int row0g = q0 + w * 16 + lm;
    const int row1g = row0g + 8;

    float qfr[16][4];
    {
        const float* q0p = Qg + (size_t)(w * 16 + lm) * D_;
        const float* q1p = q0p + 8 * D_;
#pragma unroll
        for (int dk = 0; dk < 16; dk++) {
            int col = dk * 8 + lk;
            qfr[dk][0] = to_tf32(q0p[col]);
            qfr[dk][1] = to_tf32(q1p[col]);
            qfr[dk][2] = to_tf32(q0p[col + 4]);
            qfr[dk][3] = to_tf32(q1p[col + 4]);
        }
    }

    float m0 = -1e30f, m1 = -1e30f, l0 = 0.0f, l1 = 0.0f;
    float oacc[16][4];
#pragma unroll
    for (int ni = 0; ni < 16; ni++)
#pragma unroll
        for (int r = 0; r < 4; r++) oacc[ni][r] = 0.0f;

    const float scale = 0.08838834764831845f;
    const int nkv = (q0 + 64) / 32;

    for (int kt = 0; kt < nkv; kt++) {
        const int kv0 = kt * 32;
        __syncthreads();
#pragma unroll
        for (int it = 0; it < 8; it++) {
            int idx = tid + it * 128;
            int r = idx >> 5;
            int c4 = (idx & 31) * 4;
            size_t goff = (size_t)(kv0 + r) * D_ + c4;
            float4 k4 = *(const float4*)(Kg + goff);
            float4 v4 = *(const float4*)(Vg + goff);
            int dkt = c4 >> 3;
            int rhK = ((c4 & 7) >= 4) ? 1 : 0;
            {
                float* tp = &Ks[((r >> 3) * 16 + dkt) * 68 + rhK];
                int lf = (r & 7) << 2;
                tp[(lf + 0) * 2] = to_tf32(k4.x);
                tp[(lf + 1) * 2] = to_tf32(k4.y);
                tp[(lf + 2) * 2] = to_tf32(k4.z);
                tp[(lf + 3) * 2] = to_tf32(k4.w);
            }
            {
                int rhV = ((r & 7) >= 4) ? 1 : 0;
                float* tp = &Vs[((r >> 3) * 16 + dkt) * 68 + rhV];
                int dbase = c4 & 7;
                int kl = r & 3;
                tp[((dbase + 0) * 4 + kl) * 2] = to_tf32(v4.x);
                tp[((dbase + 1) * 4 + kl) * 2] = to_tf32(v4.y);
                tp[((dbase + 2) * 4 + kl) * 2] = to_tf32(v4.z);
                tp[((dbase + 3) * 4 + kl) * 2] = to_tf32(v4.w);
            }
        }
        __syncthreads();

        float sacc[4][4];
#pragma unroll
        for (int ni = 0; ni < 4; ni++)
#pragma unroll
            for (int r = 0; r < 4; r++) sacc[ni][r] = 0.0f;

#pragma unroll
        for (int dk = 0; dk < 16; dk++) {
#pragma unroll
            for (int ni = 0; ni < 4; ni++) {
                float bfr[2];
                *(float2*)bfr = *(float2*)&Ks[(ni * 16 + dk) * 68 + lane * 2];
                mma_tf32(sacc[ni], qfr[dk], bfr);
            }
        }

        const bool needMask = (kt >= 2 * qb);
#pragma unroll
        for (int ni = 0; ni < 4; ni++) {
            int c0 = kv0 + ni * 8 + 2 * lk;
#pragma unroll
            for (int r = 0; r < 4; r++) sacc[ni][r] *= scale;
            if (needMask) {
                if (c0     > row0g) sacc[ni][0] = -1e30f;
                if (c0 + 1 > row0g) sacc[ni][1] = -1e30f;
                if (c0     > row1g) sacc[ni][2] = -1e30f;
                if (c0 + 1 > row1g) sacc[ni][3] = -1e30f;
            }
        }

        float rmax0 = -1e30f, rmax1 = -1e30f;
#pragma unroll
        for (int ni = 0; ni < 4; ni++) {
            rmax0 = fmaxf(rmax0, fmaxf(sacc[ni][0], sacc[ni][1]));
            rmax1 = fmaxf(rmax1, fmaxf(sacc[ni][2], sacc[ni][3]));
        }
        rmax0 = fmaxf(rmax0, __shfl_xor_sync(0xffffffffu, rmax0, 1));
        rmax0 = fmaxf(rmax0, __shfl_xor_sync(0xffffffffu, rmax0, 2));
        rmax1 = fmaxf(rmax1, __shfl_xor_sync(0xffffffffu, rmax1, 1));
        rmax1 = fmaxf(rmax1, __shfl_xor_sync(0xffffffffu, rmax1, 2));
        float mn0 = fmaxf(m0, rmax0);
        float mn1 = fmaxf(m1, rmax1);
        float al0 = __expf(m0 - mn0);
        float al1 = __expf(m1 - mn1);
        float rs0 = 0.0f, rs1 = 0.0f;
#pragma unroll
        for (int ni = 0; ni < 4; ni++) {
            sacc[ni][0] = __expf(sacc[ni][0] - mn0);
            sacc[ni][1] = __expf(sacc[ni][1] - mn0);
            sacc[ni][2] = __expf(sacc[ni][2] - mn1);
            sacc[ni][3] = __expf(sacc[ni][3] - mn1);
            rs0 += sacc[ni][0] + sacc[ni][1];
            rs1 += sacc[ni][2] + sacc[ni][3];
        }
        rs0 += __shfl_xor_sync(0xffffffffu, rs0, 1);
        rs0 += __shfl_xor_sync(0xffffffffu, rs0, 2);
        rs1 += __shfl_xor_sync(0xffffffffu, rs1, 1);
        rs1 += __shfl_xor_sync(0xffffffffu, rs1, 2);
        l0 = l0 * al0 + rs0;
        l1 = l1 * al1 + rs1;
        m0 = mn0;
        m1 = mn1;
#pragma unroll
        for (int ni = 0; ni < 16; ni++) {
            oacc[ni][0] *= al0; oacc[ni][1] *= al0;
            oacc[ni][2] *= al1; oacc[ni][3] *= al1;
        }

#pragma unroll
        for (int ni = 0; ni < 4; ni++) {
            float* tp = &Ps[(w * 4 + ni) * 132];
            int c0 = 2 * lk;
            int lf0 = (lm << 2) | (c0 & 3);
            int rh0 = (c0 >= 4) ? 2 : 0;
            tp[lf0 * 4 + rh0]     = to_tf32(sacc[ni][0]);
            tp[lf0 * 4 + rh0 + 1] = to_tf32(sacc[ni][2]);
            int c1 = 2 * lk + 1;
            int lf1 = (lm << 2) | (c1 & 3);
            int rh1 = (c1 >= 4) ? 2 : 0;
            tp[lf1 * 4 + rh1]     = to_tf32(sacc[ni][1]);
            tp[lf1 * 4 + rh1 + 1] = to_tf32(sacc[ni][3]);
        }
        __syncwarp();

#pragma unroll
        for (int kt2 = 0; kt2 < 4; kt2++) {
            float afr[4];
            *(float4*)afr = *(float4*)&Ps[(w * 4 + kt2) * 132 + lane * 4];
#pragma unroll
            for (int ni = 0; ni < 16; ni++) {
                float bfr[2];
                *(float2*)bfr = *(float2*)&Vs[(kt2 * 16 + ni) * 68 + lane * 2];
                mma_tf32(oacc[ni], afr, bfr);
            }
        }
    }

    // ---- finalize: write g_attn in PACKED-A layout (pairs row0g,row1g) ----
    float inv0 = 1.0f / l0;
    float inv1 = 1.0f / l1;
    const size_t rowg = (size_t)b * T_ + (size_t)row0g;
    const size_t pglob = (rowg >> 4) * 8 + (rowg & 7);   // row&7 == lm
#pragma unroll
    for (int ni = 0; ni < 16; ni++) {
        int col = h * D_ + ni * 8 + 2 * lk;
        float4 v;
        v.x = to_tf32(oacc[ni][0] * inv0);   // (row0, col)
        v.y = to_tf32(oacc[ni][2] * inv1);   // (row1, col)
        v.z = to_tf32(oacc[ni][1] * inv0);   // (row0, col+1)
        v.w = to_tf32(oacc[ni][3] * inv1);   // (row1, col+1)
        *(float4*)&g_attn[(pglob * C_ + col) * 2] = v;
    }
}

// ---------------- launch -------------------------------------------------------
extern "C" void kernel_launch(void* const* d_in, const int* in_sizes, int n_in,
                              void* d_out, int out_size)
{
    const float* x      = (const float*)d_in[0];
    const float* cosg   = (const float*)d_in[1];
    const float* sing   = (const float*)d_in[2];
    const float* W_qkv  = (const float*)d_in[3];
    const float* W_proj = (const float*)d_in[4];
    float* out = (float*)d_out;

    float* qkv;    cudaGetSymbolAddress((void**)&qkv,    g_qkv);
    float* Qb;     cudaGetSymbolAddress((void**)&Qb,     g_Q);
    float* Kb;     cudaGetSymbolAddress((void**)&Kb,     g_K);
    float* Vb;     cudaGetSymbolAddress((void**)&Vb,     g_V);
    float* attn;   cudaGetSymbolAddress((void**)&attn,   g_attn);
    float* xc;     cudaGetSymbolAddress((void**)&xc,     g_xc);
    float* wqkvC;  cudaGetSymbolAddress((void**)&wqkvC,  g_wqkvC);
    float* wprojC; cudaGetSymbolAddress((void**)&wprojC, g_wprojC);

    const int M = B_ * T_;   // 4096

    cudaFuncSetAttribute(gemm_v5_kernel,
                         cudaFuncAttributeMaxDynamicSharedMemorySize, V5_SMEM_BYTES);
    cudaFuncSetAttribute(attn_mma_kernel,
                         cudaFuncAttributeMaxDynamicSharedMemorySize,
                         ATTN_SMEM_FLOATS * sizeof(float));

    // 0) pack + tf32-round operands
    {
        int na = (M * C_) / 4;                       // A chunks (pairs x k-pairs)
        pack_a_kernel<<<(na + 255) / 256, 256>>>(x, xc, C_, na);
        int nbq = (C_ * 3 * C_) / 4;
        pack_b_kernel<<<(nbq + 255) / 256, 256>>>(W_qkv, wqkvC, 3 * C_, nbq);
        int nbp = (C_ * C_) / 4;
        pack_b_kernel<<<(nbp + 255) / 256, 256>>>(W_proj, wprojC, C_, nbp);
    }

    // 1) qkv = x @ W_qkv  (packed operands)
    {
        dim3 grid(3 * C_ / V5_BN, M / V5_BM);   // (48, 32)
        gemm_v5_kernel<<<grid, 256, V5_SMEM_BYTES>>>(xc, wqkvC, qkv, M, 3 * C_, C_);
    }
    // 2) RoPE + split
    {
        dim3 grid(H_, T_, B_);
        rope_split_kernel<<<grid, 128>>>(qkv, cosg, sing, Qb, Kb, Vb);
    }
    // 3) attention -> g_attn (packed-A layout, tf32-rounded)
    {
        dim3 grid(T_ / 64, B_ * H_);            // (32, 32)
        attn_mma_kernel<<<grid, 128, ATTN_SMEM_FLOATS * sizeof(float)>>>(Qb, Kb, Vb);
    }
    // 4) out = attn @ W_proj (A already packed by attention)
    {
        dim3 grid(C_ / V5_BN, M / V5_BM);       // (16, 32)
        gemm_v5_kernel<<<grid, 256, V5_SMEM_BYTES>>>(attn, wprojC, out, M, C_, C_);
    }
}

// round 11
// speedup vs baseline: 4.9113x; 1.0609x over previous
#include <cuda_runtime.h>
#include <cstdio>
#include <cstdint>

#define B_ 2
#define T_ 2048
#define C_ 2048
#define H_ 16
#define D_ 128

// ---------------- scratch (device globals: no runtime allocation) ----------------
__device__ float g_qkv[(size_t)B_ * T_ * 3 * C_];
__device__ float g_Q[(size_t)B_ * H_ * T_ * D_];
__device__ float g_K[(size_t)B_ * H_ * T_ * D_];      // PACKED B-frag tiles
__device__ float g_V[(size_t)B_ * H_ * T_ * D_];      // PACKED B-frag tiles
__device__ float g_attn[(size_t)B_ * T_ * C_];        // PACKED-A layout
__device__ float g_xc[(size_t)B_ * T_ * C_];          // packed-A tf32 x
__device__ float g_wqkvC[(size_t)C_ * 3 * C_];        // packed-B tf32 W_qkv
__device__ float g_wprojC[(size_t)C_ * C_];           // packed-B tf32 W_proj

// ---------------- helpers -------------------------------------------------------
__device__ __forceinline__ float to_tf32(float x) {
    unsigned u;
    asm("cvt.rna.tf32.f32 %0, %1;" : "=r"(u) : "f"(x));
    return __uint_as_float(u);
}

__device__ __forceinline__ void mma_tf32(float c[4], const float a[4], const float b[2]) {
    asm volatile(
        "mma.sync.aligned.m16n8k8.row.col.f32.tf32.tf32.f32 "
        "{%0,%1,%2,%3}, {%4,%5,%6,%7}, {%8,%9}, {%0,%1,%2,%3};"
        : "+f"(c[0]), "+f"(c[1]), "+f"(c[2]), "+f"(c[3])
        : "r"(__float_as_uint(a[0])), "r"(__float_as_uint(a[1])),
          "r"(__float_as_uint(a[2])), "r"(__float_as_uint(a[3])),
          "r"(__float_as_uint(b[0])), "r"(__float_as_uint(b[1])));
}

__device__ __forceinline__ uint32_t smem_u32(const void* p) {
    uint32_t a;
    asm("{ .reg .u64 t; cvta.to.shared.u64 t, %1; cvt.u32.u64 %0, t; }" : "=r"(a) : "l"(p));
    return a;
}

#define CP_ASYNC16(dst, src) \
    asm volatile("cp.async.cg.shared.global [%0], [%1], 16;" :: "r"(dst), "l"(src) : "memory")
#define CP_COMMIT() asm volatile("cp.async.commit_group;" ::: "memory")

// ============ GEMM v5: packed operands, LDS.64 frags, BK=32, 3 stages ===========
#define V5_BM 128
#define V5_BN 128
#define V5_BK 32
#define V5_ASTR 72
#define V5_BSTR 264
#define V5_AFLOATS (64 * V5_ASTR)             // 4608
#define V5_BFLOATS (16 * V5_BSTR)             // 4224
#define V5_STAGEF (V5_AFLOATS + V5_BFLOATS)   // 8832 floats
#define V5_NST 3
#define V5_SMEM_BYTES (V5_NST * V5_STAGEF * 4)  // 105984

__global__ __launch_bounds__(256, 2) void gemm_v5_kernel(
    const float* __restrict__ Ap, const float* __restrict__ Bp, float* __restrict__ Cm,
    int M, int N, int K)
{
    extern __shared__ float sm[];

    const int tid = threadIdx.x;
    const int warp = tid >> 5;
    const int lane = tid & 31;
    const int lm = lane >> 2;
    const int lk = lane & 3;

    const int m0 = blockIdx.y * V5_BM;
    const int n0 = blockIdx.x * V5_BN;
    const int wm = (warp >> 2) * 64;
    const int wn = (warp & 3) * 32;

    const uint32_t smb = smem_u32(sm);

    float acc[4][4][4];
#pragma unroll
    for (int mi = 0; mi < 4; mi++)
#pragma unroll
        for (int ni = 0; ni < 4; ni++)
#pragma unroll
            for (int r = 0; r < 4; r++) acc[mi][ni][r] = 0.0f;

    auto load_stage = [&](int s) {
        const int k0 = s * V5_BK;
        const uint32_t base = smb + (uint32_t)((s % V5_NST) * V5_STAGEF * 4);
#pragma unroll
        for (int i = 0; i < 4; i++) {
            int id = tid + i * 256;
            int p = id >> 4, kc = id & 15;
            uint32_t dst = base + (uint32_t)((p * V5_ASTR + kc * 4) * 4);
            const float* src = Ap + ((size_t)(m0 / 2 + p) * K + k0 + kc * 2) * 2;
            CP_ASYNC16(dst, src);
        }
        const uint32_t bbase = base + V5_AFLOATS * 4;
#pragma unroll
        for (int i = 0; i < 4; i++) {
            int id = tid + i * 256;
            int kp = id >> 6, nc = id & 63;
            uint32_t dst = bbase + (uint32_t)((kp * V5_BSTR + nc * 4) * 4);
            const float* src = Bp + ((size_t)(k0 / 2 + kp) * N + n0 + nc * 2) * 2;
            CP_ASYNC16(dst, src);
        }
        CP_COMMIT();
    };

    const int nst = K / V5_BK;   // 64
    load_stage(0);
    load_stage(1);

    for (int ks = 0; ks < nst; ks++) {
        asm volatile("cp.async.wait_group %0;" :: "n"(1) : "memory");
        __syncthreads();

        const float* As = sm + (size_t)(ks % V5_NST) * V5_STAGEF;
        const float* Bs = As + V5_AFLOATS;

#pragma unroll
        for (int kk = 0; kk < V5_BK; kk += 8) {
            float afr[4][4];
#pragma unroll
            for (int mi = 0; mi < 4; mi++) {
                int aw = (((wm >> 4) + mi) * 8 + lm) * V5_ASTR + (kk + lk) * 2;
                *(float2*)&afr[mi][0] = *(const float2*)&As[aw];
                *(float2*)&afr[mi][2] = *(const float2*)&As[aw + 8];
            }
            float bfr[4][2];
#pragma unroll
            for (int ni = 0; ni < 4; ni++) {
                int bw = ((kk >> 3) * 4 + lk) * V5_BSTR + (wn + ni * 8 + lm) * 2;
                *(float2*)&bfr[ni][0] = *(const float2*)&Bs[bw];
            }
#pragma unroll
            for (int mi = 0; mi < 4; mi++)
#pragma unroll
                for (int ni = 0; ni < 4; ni++)
                    mma_tf32(acc[mi][ni], afr[mi], bfr[ni]);
        }

        if (ks + 2 < nst) load_stage(ks + 2);
        else CP_COMMIT();
    }

#pragma unroll
    for (int mi = 0; mi < 4; mi++) {
#pragma unroll
        for (int ni = 0; ni < 4; ni++) {
            int gr = m0 + wm + mi * 16 + lm;
            int gc = n0 + wn + ni * 8 + lk * 2;
            float* p0 = Cm + (size_t)gr * N + gc;
            float* p1 = Cm + (size_t)(gr + 8) * N + gc;
            *(float2*)p0 = make_float2(acc[mi][ni][0], acc[mi][ni][1]);
            *(float2*)p1 = make_float2(acc[mi][ni][2], acc[mi][ni][3]);
        }
    }
}

// ---------------- pack pre-passes (tf32-round + layout) -------------------------
__global__ __launch_bounds__(256) void pack_a_kernel(
    const float* __restrict__ src, float* __restrict__ dst, int K, int nchunk)
{
    int c = blockIdx.x * blockDim.x + threadIdx.x;
    if (c >= nchunk) return;
    int kh = K >> 1;
    int p = c / kh, kc = c - p * kh;
    int m = (p >> 3) * 16 + (p & 7);
    int k = kc * 2;
    const float* r0 = src + (size_t)m * K + k;
    const float* r1 = r0 + (size_t)8 * K;
    float4 v;
    v.x = to_tf32(r0[0]); v.y = to_tf32(r1[0]);
    v.z = to_tf32(r0[1]); v.w = to_tf32(r1[1]);
    *(float4*)(dst + (size_t)c * 4) = v;
}

__global__ __launch_bounds__(256) void pack_b_kernel(
    const float* __restrict__ src, float* __restrict__ dst, int N, int nchunk)
{
    int c = blockIdx.x * blockDim.x + threadIdx.x;
    if (c >= nchunk) return;
    int nh = N >> 1;
    int kp = c / nh, nc = c - kp * nh;
    int k = (kp >> 2) * 8 + (kp & 3);
    int n = nc * 2;
    const float* r0 = src + (size_t)k * N + n;
    const float* r1 = r0 + (size_t)4 * N;
    float4 v;
    v.x = to_tf32(r0[0]); v.y = to_tf32(r1[0]);
    v.z = to_tf32(r0[1]); v.w = to_tf32(r1[1]);
    *(float4*)(dst + (size_t)c * 4) = v;
}

// ---------------- RoPE + pack K/V into B-fragment tile images -------------------
// Block = one 32-row KV tile of one (b,h). K/V written as 64 subtiles x 64 floats:
//   K: sub = (r>>3)*16 + (d>>3), off = ((r&7)*4 + (d&3))*2 + ((d>>2)&1)
//   V: sub = (r>>3)*16 + (d>>3), off = ((d&7)*4 + (r&3))*2 + ((r>>2)&1)
__global__ __launch_bounds__(256) void rope_pack_kernel(
    const float* __restrict__ qkv, const float* __restrict__ cosg,
    const float* __restrict__ sing,
    float* __restrict__ Q, float* __restrict__ Kp, float* __restrict__ Vp)
{
    __shared__ float stK[4096];
    __shared__ float stV[4096];
    const int kt = blockIdx.x;       // 0..63
    const int h = blockIdx.y;
    const int b = blockIdx.z;
    const int tid = threadIdx.x;
    const int t0 = kt * 32;
    const size_t bh = (size_t)(b * H_ + h);

    // Q (rope, normal layout) + K (rope, packed): 2048 (r,d) pairs, d<64
#pragma unroll
    for (int i = 0; i < 8; i++) {
        int idx = tid + i * 256;
        int r = idx >> 6, d = idx & 63;
        int t = t0 + r;
        const float* base = qkv + ((size_t)(b * T_ + t)) * (3 * C_) + h * D_;
        float c = cosg[t * 64 + d];
        float s = sing[t * 64 + d];
        float q1 = base[d], q2 = base[d + 64];
        float* Qrow = Q + (bh * T_ + t) * D_;
        Qrow[d]      = q1 * c - q2 * s;
        Qrow[d + 64] = q1 * s + q2 * c;
        float k1 = base[C_ + d], k2 = base[C_ + d + 64];
        float kr1 = to_tf32(k1 * c - k2 * s);
        float kr2 = to_tf32(k1 * s + k2 * c);
        stK[((r >> 3) * 16 + (d >> 3)) * 64 + ((r & 7) * 4 + (d & 3)) * 2 + ((d >> 2) & 1)] = kr1;
        int d2 = d + 64;
        stK[((r >> 3) * 16 + (d2 >> 3)) * 64 + ((r & 7) * 4 + (d2 & 3)) * 2 + ((d2 >> 2) & 1)] = kr2;
    }
    // V (packed): 4096 elements
#pragma unroll
    for (int i = 0; i < 16; i++) {
        int idx = tid + i * 256;
        int r = idx >> 7, d = idx & 127;
        int t = t0 + r;
        const float* base = qkv + ((size_t)(b * T_ + t)) * (3 * C_) + h * D_;
        float v = to_tf32(base[2 * C_ + d]);
        stV[((r >> 3) * 16 + (d >> 3)) * 64 + ((d & 7) * 4 + (r & 3)) * 2 + ((r >> 2) & 1)] = v;
    }
    __syncthreads();
    float* kout = Kp + bh * ((size_t)T_ * D_) + (size_t)kt * 4096;
    float* vout = Vp + bh * ((size_t)T_ * D_) + (size_t)kt * 4096;
#pragma unroll
    for (int i = 0; i < 4; i++) {
        int c = tid + i * 256;
        *(float4*)(kout + c * 4) = *(const float4*)(stK + c * 4);
        *(float4*)(vout + c * 4) = *(const float4*)(stV + c * 4);
    }
}

// ---------------- attention v3: Q in regs, cp.async packed K/V, double-buffered --
#define KV_TILE_F (64 * 68)                     // 4352 floats per K or V slot
#define PS_FLOATS (16 * 132)
#define ATTN_SMEM_FLOATS (2 * 2 * KV_TILE_F + PS_FLOATS)   // 19520 fl = 78080 B

__global__ __launch_bounds__(128, 2) void attn_mma_kernel(
    const float* __restrict__ Q, const float* __restrict__ Kp,
    const float* __restrict__ Vp)
{
    extern __shared__ float sm[];
    float* Ps = sm + 2 * 2 * KV_TILE_F;

    const int qb = blockIdx.x;
    const int bh = blockIdx.y;
    const int b = bh >> 4;
    const int h = bh & 15;
    const int tid = threadIdx.x;
    const int w = tid >> 5;
    const int lane = tid & 31;
    const int lm = lane >> 2;
    const int lk = lane & 3;
    const int q0 = qb * 64;

    const float* Qg = Q + ((size_t)bh * T_ + q0) * D_;
    const float* Kg = Kp + (size_t)bh * T_ * D_;
    const float* Vg = Vp + (size_t)bh * T_ * D_;
    const uint32_t smb = smem_u32(sm);

    const int row0g = q0 + w * 16 + lm;
    const int row1g = row0g + 8;

    // Q fragments to registers (tf32-rounded)
    float qfr[16][4];
    {
        const float* q0p = Qg + (size_t)(w * 16 + lm) * D_;
        const float* q1p = q0p + 8 * D_;
#pragma unroll
        for (int dk = 0; dk < 16; dk++) {
            int col = dk * 8 + lk;
            qfr[dk][0] = to_tf32(q0p[col]);
            qfr[dk][1] = to_tf32(q1p[col]);
            qfr[dk][2] = to_tf32(q0p[col + 4]);
            qfr[dk][3] = to_tf32(q1p[col + 4]);
        }
    }

    float m0 = -1e30f, m1 = -1e30f, l0 = 0.0f, l1 = 0.0f;
    float oacc[16][4];
#pragma unroll
    for (int ni = 0; ni < 16; ni++)
#pragma unroll
        for (int r = 0; r < 4; r++) oacc[ni][r] = 0.0f;

    const float scale = 0.08838834764831845f;
    const int nkv = (q0 + 64) / 32;

    // KV tile loader: 16 cp.async per thread (K + V)
    auto load_kv = [&](int kt) {
        const uint32_t dstb = smb + (uint32_t)((kt & 1) * 2 * KV_TILE_F * 4);
        const float* ksrc = Kg + (size_t)kt * 4096;
        const float* vsrc = Vg + (size_t)kt * 4096;
#pragma unroll
        for (int i = 0; i < 8; i++) {
            int c = tid + i * 128;
            int sub = c >> 4, q = c & 15;
            uint32_t off = (uint32_t)((sub * 68 + q * 4) * 4);
            CP_ASYNC16(dstb + off, ksrc + c * 4);
            CP_ASYNC16(dstb + KV_TILE_F * 4 + off, vsrc + c * 4);
        }
        CP_COMMIT();
    };

    load_kv(0);

    for (int kt = 0; kt < nkv; kt++) {
        const int kv0 = kt * 32;
        asm volatile("cp.async.wait_group 0;" ::: "memory");
        __syncthreads();
        if (kt + 1 < nkv) load_kv(kt + 1);

        const float* Ks = sm + (kt & 1) * 2 * KV_TILE_F;
        const float* Vs = Ks + KV_TILE_F;

        float sacc[4][4];
#pragma unroll
        for (int ni = 0; ni < 4; ni++)
#pragma unroll
            for (int r = 0; r < 4; r++) sacc[ni][r] = 0.0f;

#pragma unroll
        for (int dk = 0; dk < 16; dk++) {
#pragma unroll
            for (int ni = 0; ni < 4; ni++) {
                float bfr[2];
                *(float2*)bfr = *(float2*)&Ks[(ni * 16 + dk) * 68 + lane * 2];
                mma_tf32(sacc[ni], qfr[dk], bfr);
            }
        }

        const bool needMask = (kt >= 2 * qb);
#pragma unroll
        for (int ni = 0; ni < 4; ni++) {
            int c0 = kv0 + ni * 8 + 2 * lk;
#pragma unroll
            for (int r = 0; r < 4; r++) sacc[ni][r] *= scale;
            if (needMask) {
                if (c0     > row0g) sacc[ni][0] = -1e30f;
                if (c0 + 1 > row0g) sacc[ni][1] = -1e30f;
                if (c0     > row1g) sacc[ni][2] = -1e30f;
                if (c0 + 1 > row1g) sacc[ni][3] = -1e30f;
            }
        }

        float rmax0 = -1e30f, rmax1 = -1e30f;
#pragma unroll
        for (int ni = 0; ni < 4; ni++) {
            rmax0 = fmaxf(rmax0, fmaxf(sacc[ni][0], sacc[ni][1]));
            rmax1 = fmaxf(rmax1, fmaxf(sacc[ni][2], sacc[ni][3]));
        }
        rmax0 = fmaxf(rmax0, __shfl_xor_sync(0xffffffffu, rmax0, 1));
        rmax0 = fmaxf(rmax0, __shfl_xor_sync(0xffffffffu, rmax0, 2));
        rmax1 = fmaxf(rmax1, __shfl_xor_sync(0xffffffffu, rmax1, 1));
        rmax1 = fmaxf(rmax1, __shfl_xor_sync(0xffffffffu, rmax1, 2));
        float mn0 = fmaxf(m0, rmax0);
        float mn1 = fmaxf(m1, rmax1);
        float al0 = __expf(m0 - mn0);
        float al1 = __expf(m1 - mn1);
        float rs0 = 0.0f, rs1 = 0.0f;
#pragma unroll
        for (int ni = 0; ni < 4; ni++) {
            sacc[ni][0] = __expf(sacc[ni][0] - mn0);
            sacc[ni][1] = __expf(sacc[ni][1] - mn0);
            sacc[ni][2] = __expf(sacc[ni][2] - mn1);
            sacc[ni][3] = __expf(sacc[ni][3] - mn1);
            rs0 += sacc[ni][0] + sacc[ni][1];
            rs1 += sacc[ni][2] + sacc[ni][3];
        }
        rs0 += __shfl_xor_sync(0xffffffffu, rs0, 1);
        rs0 += __shfl_xor_sync(0xffffffffu, rs0, 2);
        rs1 += __shfl_xor_sync(0xffffffffu, rs1, 1);
        rs1 += __shfl_xor_sync(0xffffffffu, rs1, 2);
        l0 = l0 * al0 + rs0;
        l1 = l1 * al1 + rs1;
        m0 = mn0;
        m1 = mn1;
#pragma unroll
        for (int ni = 0; ni < 16; ni++) {
            oacc[ni][0] *= al0; oacc[ni][1] *= al0;
            oacc[ni][2] *= al1; oacc[ni][3] *= al1;
        }

#pragma unroll
        for (int ni = 0; ni < 4; ni++) {
            float* tp = &Ps[(w * 4 + ni) * 132];
            int c0 = 2 * lk;
            int lf0 = (lm << 2) | (c0 & 3);
            int rh0 = (c0 >= 4) ? 2 : 0;
            tp[lf0 * 4 + rh0]     = to_tf32(sacc[ni][0]);
            tp[lf0 * 4 + rh0 + 1] = to_tf32(sacc[ni][2]);
            int c1 = 2 * lk + 1;
            int lf1 = (lm << 2) | (c1 & 3);
            int rh1 = (c1 >= 4) ? 2 : 0;
            tp[lf1 * 4 + rh1]     = to_tf32(sacc[ni][1]);
            tp[lf1 * 4 + rh1 + 1] = to_tf32(sacc[ni][3]);
        }
        __syncwarp();

#pragma unroll
        for (int kt2 = 0; kt2 < 4; kt2++) {
            float afr[4];
            *(float4*)afr = *(float4*)&Ps[(w * 4 + kt2) * 132 + lane * 4];
#pragma unroll
            for (int ni = 0; ni < 16; ni++) {
                float bfr[2];
                *(float2*)bfr = *(float2*)&Vs[(kt2 * 16 + ni) * 68 + lane * 2];
                mma_tf32(oacc[ni], afr, bfr);
            }
        }
    }

    // finalize: write g_attn in PACKED-A layout
    float inv0 = 1.0f / l0;
    float inv1 = 1.0f / l1;
    const size_t rowg = (size_t)b * T_ + (size_t)row0g;
    const size_t pglob = (rowg >> 4) * 8 + (rowg & 7);
#pragma unroll
    for (int ni = 0; ni < 16; ni++) {
        int col = h * D_ + ni * 8 + 2 * lk;
        float4 v;
        v.x = to_tf32(oacc[ni][0] * inv0);
        v.y = to_tf32(oacc[ni][2] * inv1);
        v.z = to_tf32(oacc[ni][1] * inv0);
        v.w = to_tf32(oacc[ni][3] * inv1);
        *(float4*)&g_attn[(pglob * C_ + col) * 2] = v;
    }
}

// ---------------- launch -------------------------------------------------------
extern "C" void kernel_launch(void* const* d_in, const int* in_sizes, int n_in,
                              void* d_out, int out_size)
{
    const float* x      = (const float*)d_in[0];
    const float* cosg   = (const float*)d_in[1];
    const float* sing   = (const float*)d_in[2];
    const float* W_qkv  = (const float*)d_in[3];
    const float* W_proj = (const float*)d_in[4];
    float* out = (float*)d_out;

    float* qkv;    cudaGetSymbolAddress((void**)&qkv,    g_qkv);
    float* Qb;     cudaGetSymbolAddress((void**)&Qb,     g_Q);
    float* Kb;     cudaGetSymbolAddress((void**)&Kb,     g_K);
    float* Vb;     cudaGetSymbolAddress((void**)&Vb,     g_V);
    float* attn;   cudaGetSymbolAddress((void**)&attn,   g_attn);
    float* xc;     cudaGetSymbolAddress((void**)&xc,     g_xc);
    float* wqkvC;  cudaGetSymbolAddress((void**)&wqkvC,  g_wqkvC);
    float* wprojC; cudaGetSymbolAddress((void**)&wprojC, g_wprojC);

    const int M = B_ * T_;   // 4096

    cudaFuncSetAttribute(gemm_v5_kernel,
                         cudaFuncAttributeMaxDynamicSharedMemorySize, V5_SMEM_BYTES);
    cudaFuncSetAttribute(attn_mma_kernel,
                         cudaFuncAttributeMaxDynamicSharedMemorySize,
                         ATTN_SMEM_FLOATS * sizeof(float));

    // 0) pack + tf32-round operands
    {
        int na = (M * C_) / 4;
        pack_a_kernel<<<(na + 255) / 256, 256>>>(x, xc, C_, na);
        int nbq = (C_ * 3 * C_) / 4;
        pack_b_kernel<<<(nbq + 255) / 256, 256>>>(W_qkv, wqkvC, 3 * C_, nbq);
        int nbp = (C_ * C_) / 4;
        pack_b_kernel<<<(nbp + 255) / 256, 256>>>(W_proj, wprojC, C_, nbp);
    }

    // 1) qkv = x @ W_qkv
    {
        dim3 grid(3 * C_ / V5_BN, M / V5_BM);   // (48, 32)
        gemm_v5_kernel<<<grid, 256, V5_SMEM_BYTES>>>(xc, wqkvC, qkv, M, 3 * C_, C_);
    }
    // 2) RoPE + pack K/V tiles
    {
        dim3 grid(T_ / 32, H_, B_);             // (64, 16, 2)
        rope_pack_kernel<<<grid, 256>>>(qkv, cosg, sing, Qb, Kb, Vb);
    }
    // 3) attention -> g_attn (packed-A), cp.async KV pipeline
    {
        dim3 grid(T_ / 64, B_ * H_);            // (32, 32)
        attn_mma_kernel<<<grid, 128, ATTN_SMEM_FLOATS * sizeof(float)>>>(Qb, Kb, Vb);
    }
    // 4) out = attn @ W_proj
    {
        dim3 grid(C_ / V5_BN, M / V5_BM);       // (16, 32)
        gemm_v5_kernel<<<grid, 256, V5_SMEM_BYTES>>>(attn, wprojC, out, M, C_, C_);
    }
}